// round 9
// baseline (speedup 1.0000x reference)
#include <cuda_runtime.h>
#include <cuda_bf16.h>
#include <cstdint>
#include <cstddef>

// Problem constants (fixed shapes from reference)
#define BATCH 4
#define SEQ   2048
#define CDIM  1024
#define NHEAD 16
#define HDIM  64
#define MROWS (BATCH * SEQ)          // 8192

// ---------------------------------------------------------------------------
// Scratch (static device globals; no allocation allowed)
// ---------------------------------------------------------------------------
__device__ float g_q[(size_t)MROWS * CDIM];
__device__ float g_k[(size_t)MROWS * CDIM];
__device__ float g_v[(size_t)MROWS * CDIM];
__device__ float g_y[(size_t)MROWS * CDIM];

__device__ __nv_bfloat16 g_xhi[(size_t)MROWS * CDIM];
__device__ __nv_bfloat16 g_xlo[(size_t)MROWS * CDIM];
__device__ __nv_bfloat16 g_yhi[(size_t)MROWS * CDIM];
__device__ __nv_bfloat16 g_ylo[(size_t)MROWS * CDIM];
__device__ __nv_bfloat16 g_whi[4 * (size_t)CDIM * CDIM];
__device__ __nv_bfloat16 g_wlo[4 * (size_t)CDIM * CDIM];

// ---------------------------------------------------------------------------
// fp32 -> (bf16 hi, bf16 lo) split conversion. n divisible by 4.
// ---------------------------------------------------------------------------
__global__ __launch_bounds__(256)
void cvt_bf16x2_kernel(const float4* __restrict__ x,
                       __nv_bfloat162* __restrict__ hi,
                       __nv_bfloat162* __restrict__ lo, int n4)
{
    int i = blockIdx.x * blockDim.x + threadIdx.x;
    if (i >= n4) return;
    float4 v = x[i];
    __nv_bfloat16 h0 = __float2bfloat16(v.x);
    __nv_bfloat16 h1 = __float2bfloat16(v.y);
    __nv_bfloat16 h2 = __float2bfloat16(v.z);
    __nv_bfloat16 h3 = __float2bfloat16(v.w);
    __nv_bfloat16 l0 = __float2bfloat16(v.x - __bfloat162float(h0));
    __nv_bfloat16 l1 = __float2bfloat16(v.y - __bfloat162float(h1));
    __nv_bfloat16 l2 = __float2bfloat16(v.z - __bfloat162float(h2));
    __nv_bfloat16 l3 = __float2bfloat16(v.w - __bfloat162float(h3));
    hi[i * 2 + 0] = __nv_bfloat162(h0, h1);
    hi[i * 2 + 1] = __nv_bfloat162(h2, h3);
    lo[i * 2 + 0] = __nv_bfloat162(l0, l1);
    lo[i * 2 + 1] = __nv_bfloat162(l2, l3);
}

// ---------------------------------------------------------------------------
// MMA helpers (legacy warp-level tensor core path; valid on compute_103 PTX)
// ---------------------------------------------------------------------------
__device__ __forceinline__ uint32_t smem_u32(const void* p) {
    return (uint32_t)__cvta_generic_to_shared(p);
}

__device__ __forceinline__ void ldsm_x4(uint32_t addr, uint32_t& r0, uint32_t& r1,
                                        uint32_t& r2, uint32_t& r3) {
    asm volatile("ldmatrix.sync.aligned.m8n8.x4.shared.b16 {%0,%1,%2,%3}, [%4];"
                 : "=r"(r0), "=r"(r1), "=r"(r2), "=r"(r3) : "r"(addr));
}

__device__ __forceinline__ void mma_bf16(float* c, uint32_t a0, uint32_t a1,
                                         uint32_t a2, uint32_t a3,
                                         uint32_t b0, uint32_t b1) {
    asm volatile(
        "mma.sync.aligned.m16n8k16.row.col.f32.bf16.bf16.f32 "
        "{%0,%1,%2,%3}, {%4,%5,%6,%7}, {%8,%9}, {%0,%1,%2,%3};"
        : "+f"(c[0]), "+f"(c[1]), "+f"(c[2]), "+f"(c[3])
        : "r"(a0), "r"(a1), "r"(a2), "r"(a3), "r"(b0), "r"(b1));
}

__device__ __forceinline__ void mma_tf32(float* c, uint32_t a0, uint32_t a1,
                                         uint32_t a2, uint32_t a3,
                                         uint32_t b0, uint32_t b1) {
    asm volatile(
        "mma.sync.aligned.m16n8k8.row.col.f32.tf32.tf32.f32 "
        "{%0,%1,%2,%3}, {%4,%5,%6,%7}, {%8,%9}, {%0,%1,%2,%3};"
        : "+f"(c[0]), "+f"(c[1]), "+f"(c[2]), "+f"(c[3])
        : "r"(a0), "r"(a1), "r"(a2), "r"(a3), "r"(b0), "r"(b1));
}

__device__ __forceinline__ uint32_t f2tf32(float x) {
    uint32_t r;
    asm volatile("cvt.rna.tf32.f32 %0, %1;" : "=r"(r) : "f"(x));
    return r;
}
__device__ __forceinline__ float round_tf32f(float x) {
    return __uint_as_float(f2tf32(x));
}

__device__ __forceinline__ void cp_async16(uint32_t smem_dst, const void* gmem_src) {
    asm volatile("cp.async.cg.shared.global [%0], [%1], 16;"
                 :: "r"(smem_dst), "l"(gmem_src) : "memory");
}

// ---------------------------------------------------------------------------
// bf16x3 GEMM (NT): C[m,n] = sum_k A[m,k]*B[n,k], fp32 out.
// C = Ah*Bh + Ah*Bl + Al*Bh with fp32 mma accumulators.
// Tile: 128x128, BK=64 bf16. 8 warps in 4(m) x 2(n); warp tile 32x64.
// 2-stage cp.async pipeline: prefetch chunk ch+1 while computing chunk ch.
// Smem rows padded to 72 bf16 (144B) -> conflict-free ldmatrix.
// ---------------------------------------------------------------------------
#define GBK       64
#define LDS_STR   72                      // bf16 elements per smem row
#define LDS_STRB  (LDS_STR * 2)           // 144 bytes
#define TILE_B    (128 * LDS_STRB)        // 18432 bytes per operand tile
#define OFF_AHI   0
#define OFF_ALO   (1 * TILE_B)
#define OFF_BHI   (2 * TILE_B)
#define OFF_BLO   (3 * TILE_B)
#define STAGE_B   (4 * TILE_B)            // 73728 bytes per stage
#define GEMM_SMEM (2 * STAGE_B)           // 147456 bytes

__global__ __launch_bounds__(256, 1)
void gemm_mma_kernel(const __nv_bfloat16* __restrict__ Ahi,
                     const __nv_bfloat16* __restrict__ Alo,
                     const __nv_bfloat16* __restrict__ Bhi,
                     const __nv_bfloat16* __restrict__ Blo,
                     float* __restrict__ C, int M, int N, int K)
{
    extern __shared__ char sm[];
    const int tid  = threadIdx.x;
    const int warp = tid >> 5;
    const int lane = tid & 31;
    const int wm   = warp & 3;            // 0..3  (m direction, 32 rows each)
    const int wn   = warp >> 2;           // 0..1  (n direction, 64 cols each)
    const int m0   = blockIdx.y * 128;
    const int n0   = blockIdx.x * 128;

    const uint32_t sbase = smem_u32(sm);

    float acc[2][8][4];
#pragma unroll
    for (int i = 0; i < 2; i++)
#pragma unroll
        for (int j = 0; j < 8; j++)
#pragma unroll
            for (int t = 0; t < 4; t++) acc[i][j][t] = 0.0f;

    const char* pAh = (const char*)(Ahi + (size_t)m0 * K);
    const char* pAl = (const char*)(Alo + (size_t)m0 * K);
    const char* pBh = (const char*)(Bhi + (size_t)n0 * K);
    const char* pBl = (const char*)(Blo + (size_t)n0 * K);
    const size_t rowb = (size_t)K * 2;

    const int lrow = lane & 15;
    const int lcol = (lane >> 4) * 16;
    const int nch  = K / GBK;

    // prefetch one K-chunk into stage s
    auto prefetch = [&](int ch, int s) {
        const size_t koff = (size_t)ch * (GBK * 2);   // bytes
        const uint32_t sb = sbase + s * STAGE_B;
#pragma unroll
        for (int it = 0; it < 4; it++) {
            int i  = tid + it * 256;       // 0..1023
            int r  = i >> 3;
            int cb = (i & 7) * 16;
            size_t   go = (size_t)r * rowb + koff + cb;
            uint32_t so = r * LDS_STRB + cb;
            cp_async16(sb + OFF_AHI + so, pAh + go);
            cp_async16(sb + OFF_ALO + so, pAl + go);
            cp_async16(sb + OFF_BHI + so, pBh + go);
            cp_async16(sb + OFF_BLO + so, pBl + go);
        }
        asm volatile("cp.async.commit_group;" ::: "memory");
    };

    prefetch(0, 0);

    for (int ch = 0; ch < nch; ch++) {
        // wait for chunk ch's loads, then let everyone pass
        asm volatile("cp.async.wait_group 0;" ::: "memory");
        __syncthreads();
        // prefetch next chunk into the other stage (its prior compute is done)
        if (ch + 1 < nch) prefetch(ch + 1, (ch + 1) & 1);

        const uint32_t sb = sbase + (ch & 1) * STAGE_B;
#pragma unroll
        for (int kk = 0; kk < GBK / 16; kk++) {
            const uint32_t kbyte = kk * 32 + lcol;
            uint32_t bh[8][2], bl[8][2];
#pragma unroll
            for (int np = 0; np < 4; np++) {
                uint32_t baddr = sb + OFF_BHI +
                                 (wn * 64 + np * 16 + lrow) * LDS_STRB + kbyte;
                ldsm_x4(baddr, bh[np * 2][0], bh[np * 2 + 1][0],
                               bh[np * 2][1], bh[np * 2 + 1][1]);
                uint32_t laddr = baddr + (OFF_BLO - OFF_BHI);
                ldsm_x4(laddr, bl[np * 2][0], bl[np * 2 + 1][0],
                               bl[np * 2][1], bl[np * 2 + 1][1]);
            }
#pragma unroll
            for (int mt = 0; mt < 2; mt++) {
                uint32_t aaddr = sb + OFF_AHI +
                                 (wm * 32 + mt * 16 + lrow) * LDS_STRB + kbyte;
                uint32_t ah0, ah1, ah2, ah3, al0, al1, al2, al3;
                ldsm_x4(aaddr, ah0, ah1, ah2, ah3);
                ldsm_x4(aaddr + (OFF_ALO - OFF_AHI), al0, al1, al2, al3);
#pragma unroll
                for (int nt = 0; nt < 8; nt++) {
                    mma_bf16(acc[mt][nt], ah0, ah1, ah2, ah3, bh[nt][0], bh[nt][1]);
                    mma_bf16(acc[mt][nt], ah0, ah1, ah2, ah3, bl[nt][0], bl[nt][1]);
                    mma_bf16(acc[mt][nt], al0, al1, al2, al3, bh[nt][0], bh[nt][1]);
                }
            }
        }
        __syncthreads();   // all warps done with this stage before it is refilled
    }

    const int qrow = lane >> 2;
    const int qcol = (lane & 3) * 2;
#pragma unroll
    for (int mt = 0; mt < 2; mt++) {
        const int r0 = m0 + wm * 32 + mt * 16 + qrow;
#pragma unroll
        for (int nt = 0; nt < 8; nt++) {
            const int c = n0 + wn * 64 + nt * 8 + qcol;
            *reinterpret_cast<float2*>(&C[(size_t)r0 * N + c]) =
                make_float2(acc[mt][nt][0], acc[mt][nt][1]);
            *reinterpret_cast<float2*>(&C[(size_t)(r0 + 8) * N + c]) =
                make_float2(acc[mt][nt][2], acc[mt][nt][3]);
        }
    }
}

// ---------------------------------------------------------------------------
// RoPE + RMSNorm (in-place on q and k) + tf32 pre-rounding of q, k, v.
// One warp per (b,t,h) row. Outputs are stored as tf32-rounded fp32 so the
// attention kernel can feed raw bits straight into mma.tf32 with no cvt.
// ---------------------------------------------------------------------------
__global__ __launch_bounds__(128)
void rope_rms_kernel(float* __restrict__ q, float* __restrict__ k,
                     float* __restrict__ v,
                     const float* __restrict__ cs, const float* __restrict__ sn)
{
    const int gwarp = (blockIdx.x * blockDim.x + threadIdx.x) >> 5;
    const int lane  = threadIdx.x & 31;
    const int h  = gwarp & (NHEAD - 1);
    const int bt = gwarp >> 4;
    const int t  = bt & (SEQ - 1);
    const size_t base = (size_t)bt * CDIM + h * HDIM;

    const float c1 = cs[t * HDIM + lane];
    const float c2 = cs[t * HDIM + 32 + lane];
    const float s1 = sn[t * HDIM + lane];
    const float s2 = sn[t * HDIM + 32 + lane];

    {
        float x1 = q[base + lane];
        float x2 = q[base + 32 + lane];
        float r1 = x1 * c1 - x2 * s1;
        float r2 = x2 * c2 + x1 * s2;
        float ss = r1 * r1 + r2 * r2;
#pragma unroll
        for (int off = 16; off > 0; off >>= 1)
            ss += __shfl_xor_sync(0xffffffffu, ss, off);
        float inv = rsqrtf(ss * (1.0f / 64.0f) + 1e-6f);
        q[base + lane]      = round_tf32f(r1 * inv);
        q[base + 32 + lane] = round_tf32f(r2 * inv);
    }
    {
        float x1 = k[base + lane];
        float x2 = k[base + 32 + lane];
        float r1 = x1 * c1 - x2 * s1;
        float r2 = x2 * c2 + x1 * s2;
        float ss = r1 * r1 + r2 * r2;
#pragma unroll
        for (int off = 16; off > 0; off >>= 1)
            ss += __shfl_xor_sync(0xffffffffu, ss, off);
        float inv = rsqrtf(ss * (1.0f / 64.0f) + 1e-6f);
        k[base + lane]      = round_tf32f(r1 * inv);
        k[base + 32 + lane] = round_tf32f(r2 * inv);
    }
    {
        v[base + lane]      = round_tf32f(v[base + lane]);
        v[base + 32 + lane] = round_tf32f(v[base + 32 + lane]);
    }
}

// ---------------------------------------------------------------------------
// Tensor-core flash attention (tf32 mma, fp32 accum, online softmax).
// Block: 256 threads = 8 warps; each warp owns 16 q-rows (QTILE=128).
// q/k/v arrive pre-rounded to tf32 -> all fragment loads are raw lds (no cvt).
// P is tf32-rounded once when written to smem.
// ---------------------------------------------------------------------------
#define QT    128
#define KC    64
#define PSTR  68
#define ATN_SMEM ((KC + KC + QT) * PSTR * (int)sizeof(float))   // 69632

__global__ __launch_bounds__(256)
void attn_tc_kernel(const float* __restrict__ Q, const float* __restrict__ K,
                    const float* __restrict__ V, float* __restrict__ Y)
{
    extern __shared__ float smf[];
    float* Ks = smf;                   // [KC][PSTR]
    float* Vs = Ks + KC * PSTR;        // [KC][PSTR]
    float* Ps = Vs + KC * PSTR;        // [QT][PSTR]  (also Q staging)

    const int b    = blockIdx.z;
    const int h    = blockIdx.y;
    const int qt   = blockIdx.x;
    const int tid  = threadIdx.x;
    const int warp = tid >> 5;
    const int lane = tid & 31;
    const int lr   = lane >> 2;        // 0..7
    const int lc   = lane & 3;         // 0..3
    const float scale = 0.125f;        // 1/sqrt(64), exact power of two

    const float* qbase = Q + ((size_t)b * SEQ + qt * QT) * CDIM + h * HDIM;
    const float* kbase = K + (size_t)b * SEQ * CDIM + h * HDIM;
    const float* vbase = V + (size_t)b * SEQ * CDIM + h * HDIM;

    // Stage Q tile (128x64) into Ps, then build per-warp tf32 A-fragments.
    for (int i = tid; i < QT * 16; i += 256) {
        int r  = i >> 4;
        int c4 = (i & 15) * 4;
        float4 v = *reinterpret_cast<const float4*>(&qbase[(size_t)r * CDIM + c4]);
        Ps[r * PSTR + c4 + 0] = v.x; Ps[r * PSTR + c4 + 1] = v.y;
        Ps[r * PSTR + c4 + 2] = v.z; Ps[r * PSTR + c4 + 3] = v.w;
    }
    __syncthreads();

    // q pre-rounded; *0.125 preserves mantissa -> raw bits are valid tf32.
    uint32_t qa[8][4];
    {
        const float* qp = Ps + (warp * 16 + lr) * PSTR;
#pragma unroll
        for (int ks = 0; ks < 8; ks++) {
            qa[ks][0] = __float_as_uint(qp[ks * 8 + lc] * scale);
            qa[ks][1] = __float_as_uint(qp[8 * PSTR + ks * 8 + lc] * scale);
            qa[ks][2] = __float_as_uint(qp[ks * 8 + lc + 4] * scale);
            qa[ks][3] = __float_as_uint(qp[8 * PSTR + ks * 8 + lc + 4] * scale);
        }
    }

    float m[2] = {-1e30f, -1e30f};
    float l[2] = {0.0f, 0.0f};
    float o[8][4];
#pragma unroll
    for (int nt = 0; nt < 8; nt++)
#pragma unroll
        for (int j = 0; j < 4; j++) o[nt][j] = 0.0f;

    for (int kt = 0; kt < SEQ; kt += KC) {
        // Load K,V chunk (64x64 each) fp32 into smem.
        for (int i = tid; i < KC * 16; i += 256) {
            int r  = i >> 4;
            int c4 = (i & 15) * 4;
            float4 vk = *reinterpret_cast<const float4*>(&kbase[(size_t)(kt + r) * CDIM + c4]);
            Ks[r * PSTR + c4 + 0] = vk.x; Ks[r * PSTR + c4 + 1] = vk.y;
            Ks[r * PSTR + c4 + 2] = vk.z; Ks[r * PSTR + c4 + 3] = vk.w;
            float4 vv = *reinterpret_cast<const float4*>(&vbase[(size_t)(kt + r) * CDIM + c4]);
            Vs[r * PSTR + c4 + 0] = vv.x; Vs[r * PSTR + c4 + 1] = vv.y;
            Vs[r * PSTR + c4 + 2] = vv.z; Vs[r * PSTR + c4 + 3] = vv.w;
        }
        __syncthreads();

        // S = (Q*scale) @ K^T : 8 n-tiles of 8 cols, contraction D=64 (8 k8 steps)
        float p[8][4];
#pragma unroll
        for (int nt = 0; nt < 8; nt++) {
            float acc[4] = {0.0f, 0.0f, 0.0f, 0.0f};
            const float* kp = Ks + (nt * 8 + lr) * PSTR;
#pragma unroll
            for (int ks = 0; ks < 8; ks++) {
                uint32_t b0 = __float_as_uint(kp[ks * 8 + lc]);
                uint32_t b1 = __float_as_uint(kp[ks * 8 + lc + 4]);
                mma_tf32(acc, qa[ks][0], qa[ks][1], qa[ks][2], qa[ks][3], b0, b1);
            }
            p[nt][0] = acc[0]; p[nt][1] = acc[1]; p[nt][2] = acc[2]; p[nt][3] = acc[3];
        }

        // Online softmax. Register halves: {0,1} -> row lr; {2,3} -> row lr+8.
#pragma unroll
        for (int half = 0; half < 2; half++) {
            const int j0 = half * 2;
            float mx = -1e30f;
#pragma unroll
            for (int nt = 0; nt < 8; nt++)
                mx = fmaxf(mx, fmaxf(p[nt][j0], p[nt][j0 + 1]));
            mx = fmaxf(mx, __shfl_xor_sync(0xffffffffu, mx, 1));
            mx = fmaxf(mx, __shfl_xor_sync(0xffffffffu, mx, 2));
            float mnew  = fmaxf(m[half], mx);
            float alpha = __expf(m[half] - mnew);
            float rsum = 0.0f;
#pragma unroll
            for (int nt = 0; nt < 8; nt++) {
                float p0 = __expf(p[nt][j0]     - mnew);
                float p1 = __expf(p[nt][j0 + 1] - mnew);
                p[nt][j0]     = p0;
                p[nt][j0 + 1] = p1;
                rsum += p0 + p1;
            }
            rsum += __shfl_xor_sync(0xffffffffu, rsum, 1);
            rsum += __shfl_xor_sync(0xffffffffu, rsum, 2);
            l[half] = l[half] * alpha + rsum;
            m[half] = mnew;
#pragma unroll
            for (int nt = 0; nt < 8; nt++) {
                o[nt][j0]     *= alpha;
                o[nt][j0 + 1] *= alpha;
            }
        }

        // Write tf32-rounded P to smem (rows warp*16 + lr and +8)
        {
            float* pr0 = Ps + (warp * 16 + lr) * PSTR;
            float* pr1 = pr0 + 8 * PSTR;
#pragma unroll
            for (int nt = 0; nt < 8; nt++) {
                *reinterpret_cast<uint2*>(pr0 + nt * 8 + lc * 2) =
                    make_uint2(f2tf32(p[nt][0]), f2tf32(p[nt][1]));
                *reinterpret_cast<uint2*>(pr1 + nt * 8 + lc * 2) =
                    make_uint2(f2tf32(p[nt][2]), f2tf32(p[nt][3]));
            }
        }
        __syncthreads();

        // O += P @ V : contraction over 64 k-rows (8 k8 steps), 8 d-tiles
        {
            const float* pp = Ps + (warp * 16 + lr) * PSTR;
#pragma unroll
            for (int ks = 0; ks < 8; ks++) {
                uint32_t a0 = __float_as_uint(pp[ks * 8 + lc]);
                uint32_t a1 = __float_as_uint(pp[8 * PSTR + ks * 8 + lc]);
                uint32_t a2 = __float_as_uint(pp[ks * 8 + lc + 4]);
                uint32_t a3 = __float_as_uint(pp[8 * PSTR + ks * 8 + lc + 4]);
                const float* vp0 = Vs + (ks * 8 + lc) * PSTR;
                const float* vp1 = vp0 + 4 * PSTR;
#pragma unroll
                for (int nt = 0; nt < 8; nt++) {
                    uint32_t b0 = __float_as_uint(vp0[nt * 8 + lr]);
                    uint32_t b1 = __float_as_uint(vp1[nt * 8 + lr]);
                    mma_tf32(o[nt], a0, a1, a2, a3, b0, b1);
                }
            }
        }
        __syncthreads();
    }

    // Epilogue: normalize, write to Y (B,T,H,D)
    const float inv0 = 1.0f / l[0];
    const float inv1 = 1.0f / l[1];
    float* yb = Y + ((size_t)b * SEQ + qt * QT + warp * 16 + lr) * CDIM + h * HDIM;
#pragma unroll
    for (int nt = 0; nt < 8; nt++) {
        *reinterpret_cast<float2*>(yb + nt * 8 + lc * 2) =
            make_float2(o[nt][0] * inv0, o[nt][1] * inv0);
        *reinterpret_cast<float2*>(yb + 8 * CDIM + nt * 8 + lc * 2) =
            make_float2(o[nt][2] * inv1, o[nt][3] * inv1);
    }
}

// ---------------------------------------------------------------------------
// kernel_launch
// Inputs (metadata order): x, cos, sin, Wq, Wk, Wv, Wo
// ---------------------------------------------------------------------------
extern "C" void kernel_launch(void* const* d_in, const int* in_sizes, int n_in,
                              void* d_out, int out_size)
{
    const float* x   = (const float*)d_in[0];
    const float* cs  = (const float*)d_in[1];
    const float* sn  = (const float*)d_in[2];
    const float* Wq  = (const float*)d_in[3];
    const float* Wk  = (const float*)d_in[4];
    const float* Wv  = (const float*)d_in[5];
    const float* Wo  = (const float*)d_in[6];
    float* out = (float*)d_out;

    float *q, *k, *v, *y;
    cudaGetSymbolAddress((void**)&q, g_q);
    cudaGetSymbolAddress((void**)&k, g_k);
    cudaGetSymbolAddress((void**)&v, g_v);
    cudaGetSymbolAddress((void**)&y, g_y);
    __nv_bfloat16 *xhi, *xlo, *yhi, *ylo, *whi, *wlo;
    cudaGetSymbolAddress((void**)&xhi, g_xhi);
    cudaGetSymbolAddress((void**)&xlo, g_xlo);
    cudaGetSymbolAddress((void**)&yhi, g_yhi);
    cudaGetSymbolAddress((void**)&ylo, g_ylo);
    cudaGetSymbolAddress((void**)&whi, g_whi);
    cudaGetSymbolAddress((void**)&wlo, g_wlo);

    cudaFuncSetAttribute(attn_tc_kernel, cudaFuncAttributeMaxDynamicSharedMemorySize, ATN_SMEM);
    cudaFuncSetAttribute(gemm_mma_kernel, cudaFuncAttributeMaxDynamicSharedMemorySize, GEMM_SMEM);

    const size_t wsz = (size_t)CDIM * CDIM;    // 1M elements per weight

    // Split x and weights into bf16 hi/lo pairs
    {
        int n4 = (int)((size_t)MROWS * CDIM / 4);
        cvt_bf16x2_kernel<<<(n4 + 255) / 256, 256>>>(
            (const float4*)x, (__nv_bfloat162*)xhi, (__nv_bfloat162*)xlo, n4);
        int w4 = (int)(wsz / 4);
        cvt_bf16x2_kernel<<<(w4 + 255) / 256, 256>>>(
            (const float4*)Wq, (__nv_bfloat162*)(whi + 0 * wsz), (__nv_bfloat162*)(wlo + 0 * wsz), w4);
        cvt_bf16x2_kernel<<<(w4 + 255) / 256, 256>>>(
            (const float4*)Wk, (__nv_bfloat162*)(whi + 1 * wsz), (__nv_bfloat162*)(wlo + 1 * wsz), w4);
        cvt_bf16x2_kernel<<<(w4 + 255) / 256, 256>>>(
            (const float4*)Wv, (__nv_bfloat162*)(whi + 2 * wsz), (__nv_bfloat162*)(wlo + 2 * wsz), w4);
        cvt_bf16x2_kernel<<<(w4 + 255) / 256, 256>>>(
            (const float4*)Wo, (__nv_bfloat162*)(whi + 3 * wsz), (__nv_bfloat162*)(wlo + 3 * wsz), w4);
    }

    dim3 ggrid(CDIM / 128, MROWS / 128);   // (8, 64)
    gemm_mma_kernel<<<ggrid, 256, GEMM_SMEM>>>(xhi, xlo, whi + 0 * wsz, wlo + 0 * wsz, q, MROWS, CDIM, CDIM);
    gemm_mma_kernel<<<ggrid, 256, GEMM_SMEM>>>(xhi, xlo, whi + 1 * wsz, wlo + 1 * wsz, k, MROWS, CDIM, CDIM);
    gemm_mma_kernel<<<ggrid, 256, GEMM_SMEM>>>(xhi, xlo, whi + 2 * wsz, wlo + 2 * wsz, v, MROWS, CDIM, CDIM);

    int nwarps = BATCH * SEQ * NHEAD;
    rope_rms_kernel<<<nwarps / 4, 128>>>(q, k, v, cs, sn);

    dim3 agrid(SEQ / QT, NHEAD, BATCH);    // (16, 16, 4)
    attn_tc_kernel<<<agrid, 256, ATN_SMEM>>>(q, k, v, y);

    {
        int n4 = (int)((size_t)MROWS * CDIM / 4);
        cvt_bf16x2_kernel<<<(n4 + 255) / 256, 256>>>(
            (const float4*)y, (__nv_bfloat162*)yhi, (__nv_bfloat162*)ylo, n4);
    }
    gemm_mma_kernel<<<ggrid, 256, GEMM_SMEM>>>(yhi, ylo, whi + 3 * wsz, wlo + 3 * wsz, out, MROWS, CDIM, CDIM);
}

// round 10
// speedup vs baseline: 1.0602x; 1.0602x over previous
#include <cuda_runtime.h>
#include <cuda_bf16.h>
#include <cstdint>
#include <cstddef>

// Problem constants (fixed shapes from reference)
#define BATCH 4
#define SEQ   2048
#define CDIM  1024
#define NHEAD 16
#define HDIM  64
#define MROWS (BATCH * SEQ)          // 8192

// ---------------------------------------------------------------------------
// Scratch (static device globals; no allocation allowed)
// ---------------------------------------------------------------------------
__device__ float g_q[(size_t)MROWS * CDIM];
__device__ float g_k[(size_t)MROWS * CDIM];
__device__ float g_v[(size_t)MROWS * CDIM];
__device__ float g_y[(size_t)MROWS * CDIM];

__device__ __nv_bfloat16 g_xhi[(size_t)MROWS * CDIM];
__device__ __nv_bfloat16 g_xlo[(size_t)MROWS * CDIM];
__device__ __nv_bfloat16 g_yhi[(size_t)MROWS * CDIM];
__device__ __nv_bfloat16 g_ylo[(size_t)MROWS * CDIM];
__device__ __nv_bfloat16 g_whi[4 * (size_t)CDIM * CDIM];
__device__ __nv_bfloat16 g_wlo[4 * (size_t)CDIM * CDIM];

// ---------------------------------------------------------------------------
// fp32 -> (bf16 hi, bf16 lo) split conversion. n divisible by 4.
// ---------------------------------------------------------------------------
__global__ __launch_bounds__(256)
void cvt_bf16x2_kernel(const float4* __restrict__ x,
                       __nv_bfloat162* __restrict__ hi,
                       __nv_bfloat162* __restrict__ lo, int n4)
{
    int i = blockIdx.x * blockDim.x + threadIdx.x;
    if (i >= n4) return;
    float4 v = x[i];
    __nv_bfloat16 h0 = __float2bfloat16(v.x);
    __nv_bfloat16 h1 = __float2bfloat16(v.y);
    __nv_bfloat16 h2 = __float2bfloat16(v.z);
    __nv_bfloat16 h3 = __float2bfloat16(v.w);
    __nv_bfloat16 l0 = __float2bfloat16(v.x - __bfloat162float(h0));
    __nv_bfloat16 l1 = __float2bfloat16(v.y - __bfloat162float(h1));
    __nv_bfloat16 l2 = __float2bfloat16(v.z - __bfloat162float(h2));
    __nv_bfloat16 l3 = __float2bfloat16(v.w - __bfloat162float(h3));
    hi[i * 2 + 0] = __nv_bfloat162(h0, h1);
    hi[i * 2 + 1] = __nv_bfloat162(h2, h3);
    lo[i * 2 + 0] = __nv_bfloat162(l0, l1);
    lo[i * 2 + 1] = __nv_bfloat162(l2, l3);
}

// ---------------------------------------------------------------------------
// MMA helpers (legacy warp-level tensor core path; valid on compute_103 PTX)
// ---------------------------------------------------------------------------
__device__ __forceinline__ uint32_t smem_u32(const void* p) {
    return (uint32_t)__cvta_generic_to_shared(p);
}

__device__ __forceinline__ void ldsm_x4(uint32_t addr, uint32_t& r0, uint32_t& r1,
                                        uint32_t& r2, uint32_t& r3) {
    asm volatile("ldmatrix.sync.aligned.m8n8.x4.shared.b16 {%0,%1,%2,%3}, [%4];"
                 : "=r"(r0), "=r"(r1), "=r"(r2), "=r"(r3) : "r"(addr));
}

__device__ __forceinline__ void mma_bf16(float* c, uint32_t a0, uint32_t a1,
                                         uint32_t a2, uint32_t a3,
                                         uint32_t b0, uint32_t b1) {
    asm volatile(
        "mma.sync.aligned.m16n8k16.row.col.f32.bf16.bf16.f32 "
        "{%0,%1,%2,%3}, {%4,%5,%6,%7}, {%8,%9}, {%0,%1,%2,%3};"
        : "+f"(c[0]), "+f"(c[1]), "+f"(c[2]), "+f"(c[3])
        : "r"(a0), "r"(a1), "r"(a2), "r"(a3), "r"(b0), "r"(b1));
}

__device__ __forceinline__ void mma_tf32(float* c, uint32_t a0, uint32_t a1,
                                         uint32_t a2, uint32_t a3,
                                         uint32_t b0, uint32_t b1) {
    asm volatile(
        "mma.sync.aligned.m16n8k8.row.col.f32.tf32.tf32.f32 "
        "{%0,%1,%2,%3}, {%4,%5,%6,%7}, {%8,%9}, {%0,%1,%2,%3};"
        : "+f"(c[0]), "+f"(c[1]), "+f"(c[2]), "+f"(c[3])
        : "r"(a0), "r"(a1), "r"(a2), "r"(a3), "r"(b0), "r"(b1));
}

__device__ __forceinline__ uint32_t f2tf32(float x) {
    uint32_t r;
    asm volatile("cvt.rna.tf32.f32 %0, %1;" : "=r"(r) : "f"(x));
    return r;
}
__device__ __forceinline__ float round_tf32f(float x) {
    return __uint_as_float(f2tf32(x));
}

__device__ __forceinline__ void cp_async16(uint32_t smem_dst, const void* gmem_src) {
    asm volatile("cp.async.cg.shared.global [%0], [%1], 16;"
                 :: "r"(smem_dst), "l"(gmem_src) : "memory");
}
__device__ __forceinline__ void cp_async_commit_wait0() {
    asm volatile("cp.async.commit_group;" ::: "memory");
    asm volatile("cp.async.wait_group 0;" ::: "memory");
}

// ---------------------------------------------------------------------------
// bf16x3 GEMM (NT): C[m,n] = sum_k A[m,k]*B[n,k], fp32 out.
// C = Ah*Bh + Ah*Bl + Al*Bh with fp32 mma accumulators.
// Tile: 128x128, BK=64 bf16. 8 warps in 4(m) x 2(n); warp tile 32x64.
// Single-stage, 2 CTAs/SM (R5 configuration — best measured).
// Smem rows padded to 72 bf16 (144B) -> conflict-free ldmatrix.
// ---------------------------------------------------------------------------
#define GBK       64
#define LDS_STR   72                      // bf16 elements per smem row
#define LDS_STRB  (LDS_STR * 2)           // 144 bytes
#define TILE_B    (128 * LDS_STRB)        // 18432 bytes per operand tile
#define OFF_AHI   0
#define OFF_ALO   (1 * TILE_B)
#define OFF_BHI   (2 * TILE_B)
#define OFF_BLO   (3 * TILE_B)
#define GEMM_SMEM (4 * TILE_B)            // 73728 bytes

__global__ __launch_bounds__(256, 2)
void gemm_mma_kernel(const __nv_bfloat16* __restrict__ Ahi,
                     const __nv_bfloat16* __restrict__ Alo,
                     const __nv_bfloat16* __restrict__ Bhi,
                     const __nv_bfloat16* __restrict__ Blo,
                     float* __restrict__ C, int M, int N, int K)
{
    extern __shared__ char sm[];
    const int tid  = threadIdx.x;
    const int warp = tid >> 5;
    const int lane = tid & 31;
    const int wm   = warp & 3;            // 0..3  (m direction, 32 rows each)
    const int wn   = warp >> 2;           // 0..1  (n direction, 64 cols each)
    const int m0   = blockIdx.y * 128;
    const int n0   = blockIdx.x * 128;

    const uint32_t sbase = smem_u32(sm);

    float acc[2][8][4];
#pragma unroll
    for (int i = 0; i < 2; i++)
#pragma unroll
        for (int j = 0; j < 8; j++)
#pragma unroll
            for (int t = 0; t < 4; t++) acc[i][j][t] = 0.0f;

    const char* pAh = (const char*)(Ahi + (size_t)m0 * K);
    const char* pAl = (const char*)(Alo + (size_t)m0 * K);
    const char* pBh = (const char*)(Bhi + (size_t)n0 * K);
    const char* pBl = (const char*)(Blo + (size_t)n0 * K);
    const size_t rowb = (size_t)K * 2;

    const int lrow = lane & 15;
    const int lcol = (lane >> 4) * 16;

    const int nch = K / GBK;
    for (int ch = 0; ch < nch; ch++) {
        const size_t koff = (size_t)ch * (GBK * 2);   // bytes
#pragma unroll
        for (int it = 0; it < 4; it++) {
            int i  = tid + it * 256;       // 0..1023
            int r  = i >> 3;
            int cb = (i & 7) * 16;
            size_t   go = (size_t)r * rowb + koff + cb;
            uint32_t so = r * LDS_STRB + cb;
            cp_async16(sbase + OFF_AHI + so, pAh + go);
            cp_async16(sbase + OFF_ALO + so, pAl + go);
            cp_async16(sbase + OFF_BHI + so, pBh + go);
            cp_async16(sbase + OFF_BLO + so, pBl + go);
        }
        cp_async_commit_wait0();
        __syncthreads();

#pragma unroll
        for (int kk = 0; kk < GBK / 16; kk++) {
            const uint32_t kbyte = kk * 32 + lcol;
            uint32_t bh[8][2], bl[8][2];
#pragma unroll
            for (int np = 0; np < 4; np++) {
                uint32_t baddr = sbase + OFF_BHI +
                                 (wn * 64 + np * 16 + lrow) * LDS_STRB + kbyte;
                ldsm_x4(baddr, bh[np * 2][0], bh[np * 2 + 1][0],
                               bh[np * 2][1], bh[np * 2 + 1][1]);
                uint32_t laddr = baddr + (OFF_BLO - OFF_BHI);
                ldsm_x4(laddr, bl[np * 2][0], bl[np * 2 + 1][0],
                               bl[np * 2][1], bl[np * 2 + 1][1]);
            }
#pragma unroll
            for (int mt = 0; mt < 2; mt++) {
                uint32_t aaddr = sbase + OFF_AHI +
                                 (wm * 32 + mt * 16 + lrow) * LDS_STRB + kbyte;
                uint32_t ah0, ah1, ah2, ah3, al0, al1, al2, al3;
                ldsm_x4(aaddr, ah0, ah1, ah2, ah3);
                ldsm_x4(aaddr + (OFF_ALO - OFF_AHI), al0, al1, al2, al3);
#pragma unroll
                for (int nt = 0; nt < 8; nt++) {
                    mma_bf16(acc[mt][nt], ah0, ah1, ah2, ah3, bh[nt][0], bh[nt][1]);
                    mma_bf16(acc[mt][nt], ah0, ah1, ah2, ah3, bl[nt][0], bl[nt][1]);
                    mma_bf16(acc[mt][nt], al0, al1, al2, al3, bh[nt][0], bh[nt][1]);
                }
            }
        }
        __syncthreads();
    }

    const int qrow = lane >> 2;
    const int qcol = (lane & 3) * 2;
#pragma unroll
    for (int mt = 0; mt < 2; mt++) {
        const int r0 = m0 + wm * 32 + mt * 16 + qrow;
#pragma unroll
        for (int nt = 0; nt < 8; nt++) {
            const int c = n0 + wn * 64 + nt * 8 + qcol;
            *reinterpret_cast<float2*>(&C[(size_t)r0 * N + c]) =
                make_float2(acc[mt][nt][0], acc[mt][nt][1]);
            *reinterpret_cast<float2*>(&C[(size_t)(r0 + 8) * N + c]) =
                make_float2(acc[mt][nt][2], acc[mt][nt][3]);
        }
    }
}

// ---------------------------------------------------------------------------
// RoPE + RMSNorm (in-place on q and k) + tf32 pre-rounding of q, k, v.
// One warp per (b,t,h) row. Outputs are stored as tf32-rounded fp32 so the
// attention kernel can feed raw bits straight into mma.tf32 with no cvt.
// ---------------------------------------------------------------------------
__global__ __launch_bounds__(128)
void rope_rms_kernel(float* __restrict__ q, float* __restrict__ k,
                     float* __restrict__ v,
                     const float* __restrict__ cs, const float* __restrict__ sn)
{
    const int gwarp = (blockIdx.x * blockDim.x + threadIdx.x) >> 5;
    const int lane  = threadIdx.x & 31;
    const int h  = gwarp & (NHEAD - 1);
    const int bt = gwarp >> 4;
    const int t  = bt & (SEQ - 1);
    const size_t base = (size_t)bt * CDIM + h * HDIM;

    const float c1 = cs[t * HDIM + lane];
    const float c2 = cs[t * HDIM + 32 + lane];
    const float s1 = sn[t * HDIM + lane];
    const float s2 = sn[t * HDIM + 32 + lane];

    {
        float x1 = q[base + lane];
        float x2 = q[base + 32 + lane];
        float r1 = x1 * c1 - x2 * s1;
        float r2 = x2 * c2 + x1 * s2;
        float ss = r1 * r1 + r2 * r2;
#pragma unroll
        for (int off = 16; off > 0; off >>= 1)
            ss += __shfl_xor_sync(0xffffffffu, ss, off);
        float inv = rsqrtf(ss * (1.0f / 64.0f) + 1e-6f);
        q[base + lane]      = round_tf32f(r1 * inv);
        q[base + 32 + lane] = round_tf32f(r2 * inv);
    }
    {
        float x1 = k[base + lane];
        float x2 = k[base + 32 + lane];
        float r1 = x1 * c1 - x2 * s1;
        float r2 = x2 * c2 + x1 * s2;
        float ss = r1 * r1 + r2 * r2;
#pragma unroll
        for (int off = 16; off > 0; off >>= 1)
            ss += __shfl_xor_sync(0xffffffffu, ss, off);
        float inv = rsqrtf(ss * (1.0f / 64.0f) + 1e-6f);
        k[base + lane]      = round_tf32f(r1 * inv);
        k[base + 32 + lane] = round_tf32f(r2 * inv);
    }
    {
        v[base + lane]      = round_tf32f(v[base + lane]);
        v[base + 32 + lane] = round_tf32f(v[base + 32 + lane]);
    }
}

// ---------------------------------------------------------------------------
// Tensor-core flash attention (tf32 mma, fp32 accum, online softmax).
// Block: 256 threads = 8 warps; each warp owns 16 q-rows (QTILE=128).
// All fragments fed via ldmatrix.x4: an 8x8 b16 ldmatrix tile == an
// 8-row x 4-word tf32 fragment tile (thread t gets word (t/4, t%4)), which
// is exactly the m16n8k8 tf32 A/B fragment mapping. K is k-contiguous
// (native), V is stored TRANSPOSED [d][kk] at load time, P is kk-contiguous.
// q/k/v arrive pre-rounded to tf32; P is tf32-rounded at its smem store.
// ---------------------------------------------------------------------------
#define QT    128
#define KC    64
#define PSTR  68
#define PSTRB (PSTR * 4)
#define ATN_SMEM ((KC + KC + QT) * PSTR * (int)sizeof(float))   // 69632

__global__ __launch_bounds__(256)
void attn_tc_kernel(const float* __restrict__ Q, const float* __restrict__ K,
                    const float* __restrict__ V, float* __restrict__ Y)
{
    extern __shared__ float smf[];
    float* Ks = smf;                   // [KC][PSTR]   k-contiguous
    float* Vt = Ks + KC * PSTR;        // [HDIM][PSTR] TRANSPOSED: row=d, col=kk
    float* Ps = Vt + KC * PSTR;        // [QT][PSTR]   (also Q staging)

    const int b    = blockIdx.z;
    const int h    = blockIdx.y;
    const int qt   = blockIdx.x;
    const int tid  = threadIdx.x;
    const int warp = tid >> 5;
    const int lane = tid & 31;
    const int lr   = lane >> 2;        // 0..7
    const int lc   = lane & 3;         // 0..3
    const int lg   = lane >> 3;        // ldmatrix lane group 0..3
    const int li   = lane & 7;         // row within group
    const float scale = 0.125f;        // 1/sqrt(64), exact power of two

    const uint32_t ks_u = smem_u32(Ks);
    const uint32_t vt_u = smem_u32(Vt);
    const uint32_t ps_u = smem_u32(Ps);

    const float* qbase = Q + ((size_t)b * SEQ + qt * QT) * CDIM + h * HDIM;
    const float* kbase = K + (size_t)b * SEQ * CDIM + h * HDIM;
    const float* vbase = V + (size_t)b * SEQ * CDIM + h * HDIM;

    // Stage Q tile (128x64) into Ps, then build per-warp tf32 A-fragments.
    for (int i = tid; i < QT * 16; i += 256) {
        int r  = i >> 4;
        int c4 = (i & 15) * 4;
        float4 v = *reinterpret_cast<const float4*>(&qbase[(size_t)r * CDIM + c4]);
        *reinterpret_cast<float4*>(&Ps[r * PSTR + c4]) = v;
    }
    __syncthreads();

    // q pre-rounded; *0.125 preserves mantissa -> raw bits are valid tf32.
    uint32_t qa[8][4];
    {
        const float* qp = Ps + (warp * 16 + lr) * PSTR;
#pragma unroll
        for (int ks = 0; ks < 8; ks++) {
            qa[ks][0] = __float_as_uint(qp[ks * 8 + lc] * scale);
            qa[ks][1] = __float_as_uint(qp[8 * PSTR + ks * 8 + lc] * scale);
            qa[ks][2] = __float_as_uint(qp[ks * 8 + lc + 4] * scale);
            qa[ks][3] = __float_as_uint(qp[8 * PSTR + ks * 8 + lc + 4] * scale);
        }
    }

    // Per-lane ldmatrix row addresses (constant across chunks):
    // B-style tiles (K and Vt): groups 0/1 -> rows nt*8..+7, cols lo/hi;
    //                           groups 2/3 -> rows (nt+1)*8..+7, cols lo/hi.
    const uint32_t kv_row  = ((lg & 2) << 2) + li;     // +0 or +8 rows
    const uint32_t kv_col  = (lg & 1) << 4;            // +0 or +16 bytes
    // A-style tiles (P): groups 0/1 -> rows +0/+8 (k lo); groups 2/3 -> k hi.
    const uint32_t p_row   = ((lg & 1) << 3) + li;
    const uint32_t p_col   = (lg & 2) << 3;            // +0 or +16 bytes
    const uint32_t p_addr0 = ps_u + (warp * 16 + p_row) * PSTRB + p_col;

    float m[2] = {-1e30f, -1e30f};
    float l[2] = {0.0f, 0.0f};
    float o[8][4];
#pragma unroll
    for (int nt = 0; nt < 8; nt++)
#pragma unroll
        for (int j = 0; j < 4; j++) o[nt][j] = 0.0f;

    for (int kt = 0; kt < SEQ; kt += KC) {
        // Load K chunk (row-major, float4) and V chunk (transposed, scalar).
        for (int i = tid; i < KC * 16; i += 256) {
            int r  = i >> 4;
            int c4 = (i & 15) * 4;
            float4 vk = *reinterpret_cast<const float4*>(&kbase[(size_t)(kt + r) * CDIM + c4]);
            *reinterpret_cast<float4*>(&Ks[r * PSTR + c4]) = vk;
            float4 vv = *reinterpret_cast<const float4*>(&vbase[(size_t)(kt + r) * CDIM + c4]);
            Vt[(c4 + 0) * PSTR + r] = vv.x;
            Vt[(c4 + 1) * PSTR + r] = vv.y;
            Vt[(c4 + 2) * PSTR + r] = vv.z;
            Vt[(c4 + 3) * PSTR + r] = vv.w;
        }
        __syncthreads();

        // S = (Q*scale) @ K^T : ldmatrix.x4 feeds fragment pairs (nt, nt+1).
        float p[8][4];
#pragma unroll
        for (int nt = 0; nt < 8; nt++)
#pragma unroll
            for (int j = 0; j < 4; j++) p[nt][j] = 0.0f;
#pragma unroll
        for (int ntp = 0; ntp < 4; ntp++) {
            const uint32_t kaddr = ks_u + (ntp * 16 + kv_row) * PSTRB + kv_col;
#pragma unroll
            for (int ks = 0; ks < 8; ks++) {
                uint32_t b0, b1, c0, c1;
                ldsm_x4(kaddr + ks * 32, b0, b1, c0, c1);
                mma_tf32(p[2 * ntp],     qa[ks][0], qa[ks][1], qa[ks][2], qa[ks][3], b0, b1);
                mma_tf32(p[2 * ntp + 1], qa[ks][0], qa[ks][1], qa[ks][2], qa[ks][3], c0, c1);
            }
        }

        // Online softmax. Register halves: {0,1} -> row lr; {2,3} -> row lr+8.
#pragma unroll
        for (int half = 0; half < 2; half++) {
            const int j0 = half * 2;
            float mx = -1e30f;
#pragma unroll
            for (int nt = 0; nt < 8; nt++)
                mx = fmaxf(mx, fmaxf(p[nt][j0], p[nt][j0 + 1]));
            mx = fmaxf(mx, __shfl_xor_sync(0xffffffffu, mx, 1));
            mx = fmaxf(mx, __shfl_xor_sync(0xffffffffu, mx, 2));
            float mnew  = fmaxf(m[half], mx);
            float alpha = __expf(m[half] - mnew);
            float rsum = 0.0f;
#pragma unroll
            for (int nt = 0; nt < 8; nt++) {
                float p0 = __expf(p[nt][j0]     - mnew);
                float p1 = __expf(p[nt][j0 + 1] - mnew);
                p[nt][j0]     = p0;
                p[nt][j0 + 1] = p1;
                rsum += p0 + p1;
            }
            rsum += __shfl_xor_sync(0xffffffffu, rsum, 1);
            rsum += __shfl_xor_sync(0xffffffffu, rsum, 2);
            l[half] = l[half] * alpha + rsum;
            m[half] = mnew;
#pragma unroll
            for (int nt = 0; nt < 8; nt++) {
                o[nt][j0]     *= alpha;
                o[nt][j0 + 1] *= alpha;
            }
        }

        // Write tf32-rounded P to smem (rows warp*16 + lr and +8)
        {
            float* pr0 = Ps + (warp * 16 + lr) * PSTR;
            float* pr1 = pr0 + 8 * PSTR;
#pragma unroll
            for (int nt = 0; nt < 8; nt++) {
                *reinterpret_cast<uint2*>(pr0 + nt * 8 + lc * 2) =
                    make_uint2(f2tf32(p[nt][0]), f2tf32(p[nt][1]));
                *reinterpret_cast<uint2*>(pr1 + nt * 8 + lc * 2) =
                    make_uint2(f2tf32(p[nt][2]), f2tf32(p[nt][3]));
            }
        }
        __syncthreads();

        // O += P @ V : P A-fragments and Vt B-fragments all via ldmatrix.
#pragma unroll
        for (int ks = 0; ks < 8; ks++) {
            uint32_t a0, a1, a2, a3;
            ldsm_x4(p_addr0 + ks * 32, a0, a1, a2, a3);
#pragma unroll
            for (int ntp = 0; ntp < 4; ntp++) {
                const uint32_t vaddr = vt_u + (ntp * 16 + kv_row) * PSTRB + kv_col + ks * 32;
                uint32_t b0, b1, c0, c1;
                ldsm_x4(vaddr, b0, b1, c0, c1);
                mma_tf32(o[2 * ntp],     a0, a1, a2, a3, b0, b1);
                mma_tf32(o[2 * ntp + 1], a0, a1, a2, a3, c0, c1);
            }
        }
        __syncthreads();
    }

    // Epilogue: normalize, write to Y (B,T,H,D)
    const float inv0 = 1.0f / l[0];
    const float inv1 = 1.0f / l[1];
    float* yb = Y + ((size_t)b * SEQ + qt * QT + warp * 16 + lr) * CDIM + h * HDIM;
#pragma unroll
    for (int nt = 0; nt < 8; nt++) {
        *reinterpret_cast<float2*>(yb + nt * 8 + lc * 2) =
            make_float2(o[nt][0] * inv0, o[nt][1] * inv0);
        *reinterpret_cast<float2*>(yb + 8 * CDIM + nt * 8 + lc * 2) =
            make_float2(o[nt][2] * inv1, o[nt][3] * inv1);
    }
}

// ---------------------------------------------------------------------------
// kernel_launch
// Inputs (metadata order): x, cos, sin, Wq, Wk, Wv, Wo
// ---------------------------------------------------------------------------
extern "C" void kernel_launch(void* const* d_in, const int* in_sizes, int n_in,
                              void* d_out, int out_size)
{
    const float* x   = (const float*)d_in[0];
    const float* cs  = (const float*)d_in[1];
    const float* sn  = (const float*)d_in[2];
    const float* Wq  = (const float*)d_in[3];
    const float* Wk  = (const float*)d_in[4];
    const float* Wv  = (const float*)d_in[5];
    const float* Wo  = (const float*)d_in[6];
    float* out = (float*)d_out;

    float *q, *k, *v, *y;
    cudaGetSymbolAddress((void**)&q, g_q);
    cudaGetSymbolAddress((void**)&k, g_k);
    cudaGetSymbolAddress((void**)&v, g_v);
    cudaGetSymbolAddress((void**)&y, g_y);
    __nv_bfloat16 *xhi, *xlo, *yhi, *ylo, *whi, *wlo;
    cudaGetSymbolAddress((void**)&xhi, g_xhi);
    cudaGetSymbolAddress((void**)&xlo, g_xlo);
    cudaGetSymbolAddress((void**)&yhi, g_yhi);
    cudaGetSymbolAddress((void**)&ylo, g_ylo);
    cudaGetSymbolAddress((void**)&whi, g_whi);
    cudaGetSymbolAddress((void**)&wlo, g_wlo);

    cudaFuncSetAttribute(attn_tc_kernel, cudaFuncAttributeMaxDynamicSharedMemorySize, ATN_SMEM);
    cudaFuncSetAttribute(gemm_mma_kernel, cudaFuncAttributeMaxDynamicSharedMemorySize, GEMM_SMEM);

    const size_t wsz = (size_t)CDIM * CDIM;    // 1M elements per weight

    // Split x and weights into bf16 hi/lo pairs
    {
        int n4 = (int)((size_t)MROWS * CDIM / 4);
        cvt_bf16x2_kernel<<<(n4 + 255) / 256, 256>>>(
            (const float4*)x, (__nv_bfloat162*)xhi, (__nv_bfloat162*)xlo, n4);
        int w4 = (int)(wsz / 4);
        cvt_bf16x2_kernel<<<(w4 + 255) / 256, 256>>>(
            (const float4*)Wq, (__nv_bfloat162*)(whi + 0 * wsz), (__nv_bfloat162*)(wlo + 0 * wsz), w4);
        cvt_bf16x2_kernel<<<(w4 + 255) / 256, 256>>>(
            (const float4*)Wk, (__nv_bfloat162*)(whi + 1 * wsz), (__nv_bfloat162*)(wlo + 1 * wsz), w4);
        cvt_bf16x2_kernel<<<(w4 + 255) / 256, 256>>>(
            (const float4*)Wv, (__nv_bfloat162*)(whi + 2 * wsz), (__nv_bfloat162*)(wlo + 2 * wsz), w4);
        cvt_bf16x2_kernel<<<(w4 + 255) / 256, 256>>>(
            (const float4*)Wo, (__nv_bfloat162*)(whi + 3 * wsz), (__nv_bfloat162*)(wlo + 3 * wsz), w4);
    }

    dim3 ggrid(CDIM / 128, MROWS / 128);   // (8, 64)
    gemm_mma_kernel<<<ggrid, 256, GEMM_SMEM>>>(xhi, xlo, whi + 0 * wsz, wlo + 0 * wsz, q, MROWS, CDIM, CDIM);
    gemm_mma_kernel<<<ggrid, 256, GEMM_SMEM>>>(xhi, xlo, whi + 1 * wsz, wlo + 1 * wsz, k, MROWS, CDIM, CDIM);
    gemm_mma_kernel<<<ggrid, 256, GEMM_SMEM>>>(xhi, xlo, whi + 2 * wsz, wlo + 2 * wsz, v, MROWS, CDIM, CDIM);

    int nwarps = BATCH * SEQ * NHEAD;
    rope_rms_kernel<<<nwarps / 4, 128>>>(q, k, v, cs, sn);

    dim3 agrid(SEQ / QT, NHEAD, BATCH);    // (16, 16, 4)
    attn_tc_kernel<<<agrid, 256, ATN_SMEM>>>(q, k, v, y);

    {
        int n4 = (int)((size_t)MROWS * CDIM / 4);
        cvt_bf16x2_kernel<<<(n4 + 255) / 256, 256>>>(
            (const float4*)y, (__nv_bfloat162*)yhi, (__nv_bfloat162*)ylo, n4);
    }
    gemm_mma_kernel<<<ggrid, 256, GEMM_SMEM>>>(yhi, ylo, whi + 3 * wsz, wlo + 3 * wsz, out, MROWS, CDIM, CDIM);
}

// round 12
// speedup vs baseline: 1.1302x; 1.0661x over previous
#include <cuda_runtime.h>
#include <cuda_bf16.h>
#include <cstdint>
#include <cstddef>

// Problem constants (fixed shapes from reference)
#define BATCH 4
#define SEQ   2048
#define CDIM  1024
#define NHEAD 16
#define HDIM  64
#define MROWS (BATCH * SEQ)          // 8192

// ---------------------------------------------------------------------------
// Scratch (static device globals; no allocation allowed)
// ---------------------------------------------------------------------------
__device__ float g_q[(size_t)MROWS * CDIM];
__device__ float g_k[(size_t)MROWS * CDIM];
__device__ float g_v[(size_t)MROWS * CDIM];

__device__ __nv_bfloat16 g_xhi[(size_t)MROWS * CDIM];
__device__ __nv_bfloat16 g_xlo[(size_t)MROWS * CDIM];
__device__ __nv_bfloat16 g_yhi[(size_t)MROWS * CDIM];
__device__ __nv_bfloat16 g_ylo[(size_t)MROWS * CDIM];
__device__ __nv_bfloat16 g_whi[4 * (size_t)CDIM * CDIM];
__device__ __nv_bfloat16 g_wlo[4 * (size_t)CDIM * CDIM];

// ---------------------------------------------------------------------------
// fp32 -> (bf16 hi, bf16 lo) split conversion. n divisible by 4.
// ---------------------------------------------------------------------------
__global__ __launch_bounds__(256)
void cvt_bf16x2_kernel(const float4* __restrict__ x,
                       __nv_bfloat162* __restrict__ hi,
                       __nv_bfloat162* __restrict__ lo, int n4)
{
    int i = blockIdx.x * blockDim.x + threadIdx.x;
    if (i >= n4) return;
    float4 v = x[i];
    __nv_bfloat16 h0 = __float2bfloat16(v.x);
    __nv_bfloat16 h1 = __float2bfloat16(v.y);
    __nv_bfloat16 h2 = __float2bfloat16(v.z);
    __nv_bfloat16 h3 = __float2bfloat16(v.w);
    __nv_bfloat16 l0 = __float2bfloat16(v.x - __bfloat162float(h0));
    __nv_bfloat16 l1 = __float2bfloat16(v.y - __bfloat162float(h1));
    __nv_bfloat16 l2 = __float2bfloat16(v.z - __bfloat162float(h2));
    __nv_bfloat16 l3 = __float2bfloat16(v.w - __bfloat162float(h3));
    hi[i * 2 + 0] = __nv_bfloat162(h0, h1);
    hi[i * 2 + 1] = __nv_bfloat162(h2, h3);
    lo[i * 2 + 0] = __nv_bfloat162(l0, l1);
    lo[i * 2 + 1] = __nv_bfloat162(l2, l3);
}

// ---------------------------------------------------------------------------
// MMA helpers (legacy warp-level tensor core path; valid on compute_103 PTX)
// ---------------------------------------------------------------------------
__device__ __forceinline__ uint32_t smem_u32(const void* p) {
    return (uint32_t)__cvta_generic_to_shared(p);
}

__device__ __forceinline__ void ldsm_x4(uint32_t addr, uint32_t& r0, uint32_t& r1,
                                        uint32_t& r2, uint32_t& r3) {
    asm volatile("ldmatrix.sync.aligned.m8n8.x4.shared.b16 {%0,%1,%2,%3}, [%4];"
                 : "=r"(r0), "=r"(r1), "=r"(r2), "=r"(r3) : "r"(addr));
}

__device__ __forceinline__ void mma_bf16(float* c, uint32_t a0, uint32_t a1,
                                         uint32_t a2, uint32_t a3,
                                         uint32_t b0, uint32_t b1) {
    asm volatile(
        "mma.sync.aligned.m16n8k16.row.col.f32.bf16.bf16.f32 "
        "{%0,%1,%2,%3}, {%4,%5,%6,%7}, {%8,%9}, {%0,%1,%2,%3};"
        : "+f"(c[0]), "+f"(c[1]), "+f"(c[2]), "+f"(c[3])
        : "r"(a0), "r"(a1), "r"(a2), "r"(a3), "r"(b0), "r"(b1));
}

__device__ __forceinline__ void mma_tf32(float* c, uint32_t a0, uint32_t a1,
                                         uint32_t a2, uint32_t a3,
                                         uint32_t b0, uint32_t b1) {
    asm volatile(
        "mma.sync.aligned.m16n8k8.row.col.f32.tf32.tf32.f32 "
        "{%0,%1,%2,%3}, {%4,%5,%6,%7}, {%8,%9}, {%0,%1,%2,%3};"
        : "+f"(c[0]), "+f"(c[1]), "+f"(c[2]), "+f"(c[3])
        : "r"(a0), "r"(a1), "r"(a2), "r"(a3), "r"(b0), "r"(b1));
}

__device__ __forceinline__ uint32_t f2tf32(float x) {
    uint32_t r;
    asm volatile("cvt.rna.tf32.f32 %0, %1;" : "=r"(r) : "f"(x));
    return r;
}
__device__ __forceinline__ float round_tf32f(float x) {
    return __uint_as_float(f2tf32(x));
}

__device__ __forceinline__ void cp_async16(uint32_t smem_dst, const void* gmem_src) {
    asm volatile("cp.async.cg.shared.global [%0], [%1], 16;"
                 :: "r"(smem_dst), "l"(gmem_src) : "memory");
}
__device__ __forceinline__ void cp_async_commit_wait0() {
    asm volatile("cp.async.commit_group;" ::: "memory");
    asm volatile("cp.async.wait_group 0;" ::: "memory");
}

// ---------------------------------------------------------------------------
// Shared bf16x3 GEMM mainloop (NT): acc = sum_k A[m,k]*B[n,k].
// Tile: 128x128, BK=64 bf16. 8 warps in 4(m) x 2(n); warp tile 32x64.
// Smem rows padded to 72 bf16 (144B) -> conflict-free ldmatrix.
// ---------------------------------------------------------------------------
#define GBK       64
#define LDS_STR   72                      // bf16 elements per smem row
#define LDS_STRB  (LDS_STR * 2)           // 144 bytes
#define TILE_B    (128 * LDS_STRB)        // 18432 bytes per operand tile
#define OFF_AHI   0
#define OFF_ALO   (1 * TILE_B)
#define OFF_BHI   (2 * TILE_B)
#define OFF_BLO   (3 * TILE_B)
#define GEMM_SMEM (4 * TILE_B)            // 73728 bytes

__device__ __forceinline__ void gemm_mainloop(
    char* sm, uint32_t sbase, int tid, int warp, int lane,
    const char* pAh, const char* pAl, const char* pBh, const char* pBl,
    int K, float acc[2][8][4])
{
    const int wm = warp & 3;
    const int wn = warp >> 2;
    const size_t rowb = (size_t)K * 2;
    const int lrow = lane & 15;
    const int lcol = (lane >> 4) * 16;

    const int nch = K / GBK;
    for (int ch = 0; ch < nch; ch++) {
        const size_t koff = (size_t)ch * (GBK * 2);   // bytes
#pragma unroll
        for (int it = 0; it < 4; it++) {
            int i  = tid + it * 256;       // 0..1023
            int r  = i >> 3;
            int cb = (i & 7) * 16;
            size_t   go = (size_t)r * rowb + koff + cb;
            uint32_t so = r * LDS_STRB + cb;
            cp_async16(sbase + OFF_AHI + so, pAh + go);
            cp_async16(sbase + OFF_ALO + so, pAl + go);
            cp_async16(sbase + OFF_BHI + so, pBh + go);
            cp_async16(sbase + OFF_BLO + so, pBl + go);
        }
        cp_async_commit_wait0();
        __syncthreads();

#pragma unroll
        for (int kk = 0; kk < GBK / 16; kk++) {
            const uint32_t kbyte = kk * 32 + lcol;
            uint32_t bh[8][2], bl[8][2];
#pragma unroll
            for (int np = 0; np < 4; np++) {
                uint32_t baddr = sbase + OFF_BHI +
                                 (wn * 64 + np * 16 + lrow) * LDS_STRB + kbyte;
                ldsm_x4(baddr, bh[np * 2][0], bh[np * 2 + 1][0],
                               bh[np * 2][1], bh[np * 2 + 1][1]);
                uint32_t laddr = baddr + (OFF_BLO - OFF_BHI);
                ldsm_x4(laddr, bl[np * 2][0], bl[np * 2 + 1][0],
                               bl[np * 2][1], bl[np * 2 + 1][1]);
            }
#pragma unroll
            for (int mt = 0; mt < 2; mt++) {
                uint32_t aaddr = sbase + OFF_AHI +
                                 (wm * 32 + mt * 16 + lrow) * LDS_STRB + kbyte;
                uint32_t ah0, ah1, ah2, ah3, al0, al1, al2, al3;
                ldsm_x4(aaddr, ah0, ah1, ah2, ah3);
                ldsm_x4(aaddr + (OFF_ALO - OFF_AHI), al0, al1, al2, al3);
#pragma unroll
                for (int nt = 0; nt < 8; nt++) {
                    mma_bf16(acc[mt][nt], ah0, ah1, ah2, ah3, bh[nt][0], bh[nt][1]);
                    mma_bf16(acc[mt][nt], ah0, ah1, ah2, ah3, bl[nt][0], bl[nt][1]);
                    mma_bf16(acc[mt][nt], al0, al1, al2, al3, bh[nt][0], bh[nt][1]);
                }
            }
        }
        __syncthreads();
    }
}

// ---------------------------------------------------------------------------
// Fused QKV GEMM: one launch computes q, k, v (blockIdx.x>>3 selects weight).
// Epilogue applies RoPE + RMSNorm + tf32 rounding for q/k, rounding for v.
// The warp's 64-col n-tile is exactly one head; (d, d+32) live in registers
// nt and nt+4 of the same thread; RMS reduce is a quad shfl over lanes lc.
// ---------------------------------------------------------------------------
__global__ __launch_bounds__(256, 2)
void gemm_qkv_kernel(const __nv_bfloat16* __restrict__ Ahi,
                     const __nv_bfloat16* __restrict__ Alo,
                     const __nv_bfloat16* __restrict__ Whi,   // [3][CDIM*CDIM]
                     const __nv_bfloat16* __restrict__ Wlo,
                     float* __restrict__ q, float* __restrict__ k,
                     float* __restrict__ v,
                     const float* __restrict__ cs, const float* __restrict__ sn)
{
    extern __shared__ char sm[];
    const int tid  = threadIdx.x;
    const int warp = tid >> 5;
    const int lane = tid & 31;
    const int wm   = warp & 3;
    const int wn   = warp >> 2;
    const int wsel = blockIdx.x >> 3;            // 0=q, 1=k, 2=v
    const int n0   = (blockIdx.x & 7) * 128;
    const int m0   = blockIdx.y * 128;
    const int K    = CDIM;
    const size_t wsz = (size_t)CDIM * CDIM;

    const uint32_t sbase = smem_u32(sm);

    float acc[2][8][4];
#pragma unroll
    for (int i = 0; i < 2; i++)
#pragma unroll
        for (int j = 0; j < 8; j++)
#pragma unroll
            for (int t = 0; t < 4; t++) acc[i][j][t] = 0.0f;

    gemm_mainloop(sm, sbase, tid, warp, lane,
                  (const char*)(Ahi + (size_t)m0 * K),
                  (const char*)(Alo + (size_t)m0 * K),
                  (const char*)(Whi + wsel * wsz + (size_t)n0 * K),
                  (const char*)(Wlo + wsel * wsz + (size_t)n0 * K),
                  K, acc);

    float* C = (wsel == 0) ? q : (wsel == 1) ? k : v;
    const int qrow = lane >> 2;
    const int qcol = (lane & 3) * 2;

    if (wsel < 2) {
        // RoPE + RMSNorm + tf32 round. Process each of the 4 rows this
        // thread participates in: (mt, rh) -> row m0+wm*32+mt*16+qrow+rh*8,
        // register slot j0 = rh*2.
#pragma unroll
        for (int mt = 0; mt < 2; mt++) {
#pragma unroll
            for (int rh = 0; rh < 2; rh++) {
                const int j0  = rh * 2;
                const int row = m0 + wm * 32 + mt * 16 + qrow + rh * 8;
                const int t   = row & (SEQ - 1);
                const float* cst = cs + t * HDIM;
                const float* snt = sn + t * HDIM;
                // RoPE: nt<4 holds d in [0,32), nt+4 holds d+32.
#pragma unroll
                for (int nt = 0; nt < 4; nt++) {
#pragma unroll
                    for (int j = 0; j < 2; j++) {
                        const int d = nt * 8 + qcol + j;        // < 32
                        float x1 = acc[mt][nt][j0 + j];
                        float x2 = acc[mt][nt + 4][j0 + j];
                        float r1 = x1 * cst[d]      - x2 * snt[d];
                        float r2 = x2 * cst[d + 32] + x1 * snt[d + 32];
                        acc[mt][nt][j0 + j]     = r1;
                        acc[mt][nt + 4][j0 + j] = r2;
                    }
                }
                // RMSNorm over the 64-dim head: 16 vals here + quad reduce.
                float ss = 0.0f;
#pragma unroll
                for (int nt = 0; nt < 8; nt++)
                    ss += acc[mt][nt][j0] * acc[mt][nt][j0]
                        + acc[mt][nt][j0 + 1] * acc[mt][nt][j0 + 1];
                ss += __shfl_xor_sync(0xffffffffu, ss, 1);
                ss += __shfl_xor_sync(0xffffffffu, ss, 2);
                const float inv = rsqrtf(ss * (1.0f / 64.0f) + 1e-6f);
                float* crow = C + (size_t)row * CDIM + n0 + wn * 64;
#pragma unroll
                for (int nt = 0; nt < 8; nt++) {
                    *reinterpret_cast<float2*>(crow + nt * 8 + qcol) = make_float2(
                        round_tf32f(acc[mt][nt][j0] * inv),
                        round_tf32f(acc[mt][nt][j0 + 1] * inv));
                }
            }
        }
    } else {
        // v: tf32 round only
#pragma unroll
        for (int mt = 0; mt < 2; mt++) {
#pragma unroll
            for (int rh = 0; rh < 2; rh++) {
                const int j0  = rh * 2;
                const int row = m0 + wm * 32 + mt * 16 + qrow + rh * 8;
                float* crow = C + (size_t)row * CDIM + n0 + wn * 64;
#pragma unroll
                for (int nt = 0; nt < 8; nt++) {
                    *reinterpret_cast<float2*>(crow + nt * 8 + qcol) = make_float2(
                        round_tf32f(acc[mt][nt][j0]),
                        round_tf32f(acc[mt][nt][j0 + 1]));
                }
            }
        }
    }
}

// ---------------------------------------------------------------------------
// Generic bf16x3 GEMM (for the O-projection): C = A @ B^T, fp32 out.
// ---------------------------------------------------------------------------
__global__ __launch_bounds__(256, 2)
void gemm_mma_kernel(const __nv_bfloat16* __restrict__ Ahi,
                     const __nv_bfloat16* __restrict__ Alo,
                     const __nv_bfloat16* __restrict__ Bhi,
                     const __nv_bfloat16* __restrict__ Blo,
                     float* __restrict__ C, int M, int N, int K)
{
    extern __shared__ char sm[];
    const int tid  = threadIdx.x;
    const int warp = tid >> 5;
    const int lane = tid & 31;
    const int wm   = warp & 3;
    const int wn   = warp >> 2;
    const int m0   = blockIdx.y * 128;
    const int n0   = blockIdx.x * 128;

    const uint32_t sbase = smem_u32(sm);

    float acc[2][8][4];
#pragma unroll
    for (int i = 0; i < 2; i++)
#pragma unroll
        for (int j = 0; j < 8; j++)
#pragma unroll
            for (int t = 0; t < 4; t++) acc[i][j][t] = 0.0f;

    gemm_mainloop(sm, sbase, tid, warp, lane,
                  (const char*)(Ahi + (size_t)m0 * K),
                  (const char*)(Alo + (size_t)m0 * K),
                  (const char*)(Bhi + (size_t)n0 * K),
                  (const char*)(Blo + (size_t)n0 * K),
                  K, acc);

    const int qrow = lane >> 2;
    const int qcol = (lane & 3) * 2;
#pragma unroll
    for (int mt = 0; mt < 2; mt++) {
        const int r0 = m0 + wm * 32 + mt * 16 + qrow;
#pragma unroll
        for (int nt = 0; nt < 8; nt++) {
            const int c = n0 + wn * 64 + nt * 8 + qcol;
            *reinterpret_cast<float2*>(&C[(size_t)r0 * N + c]) =
                make_float2(acc[mt][nt][0], acc[mt][nt][1]);
            *reinterpret_cast<float2*>(&C[(size_t)(r0 + 8) * N + c]) =
                make_float2(acc[mt][nt][2], acc[mt][nt][3]);
        }
    }
}

// ---------------------------------------------------------------------------
// Tensor-core flash attention (tf32 mma, fp32 accum, online softmax).
// All fragments via ldmatrix.x4 (see R10). Epilogue writes bf16 hi/lo
// split of y directly (feeds the O-projection GEMM).
// ---------------------------------------------------------------------------
#define QT    128
#define KC    64
#define PSTR  68
#define PSTRB (PSTR * 4)
#define ATN_SMEM ((KC + KC + QT) * PSTR * (int)sizeof(float))   // 69632

__global__ __launch_bounds__(256)
void attn_tc_kernel(const float* __restrict__ Q, const float* __restrict__ K,
                    const float* __restrict__ V,
                    __nv_bfloat16* __restrict__ Yhi,
                    __nv_bfloat16* __restrict__ Ylo)
{
    extern __shared__ float smf[];
    float* Ks = smf;                   // [KC][PSTR]   k-contiguous
    float* Vt = Ks + KC * PSTR;        // [HDIM][PSTR] TRANSPOSED: row=d, col=kk
    float* Ps = Vt + KC * PSTR;        // [QT][PSTR]   (also Q staging)

    const int b    = blockIdx.z;
    const int h    = blockIdx.y;
    const int qt   = blockIdx.x;
    const int tid  = threadIdx.x;
    const int warp = tid >> 5;
    const int lane = tid & 31;
    const int lr   = lane >> 2;        // 0..7
    const int lc   = lane & 3;         // 0..3
    const int lg   = lane >> 3;        // ldmatrix lane group 0..3
    const int li   = lane & 7;         // row within group
    const float scale = 0.125f;        // 1/sqrt(64), exact power of two

    const uint32_t ks_u = smem_u32(Ks);
    const uint32_t vt_u = smem_u32(Vt);
    const uint32_t ps_u = smem_u32(Ps);

    const float* qbase = Q + ((size_t)b * SEQ + qt * QT) * CDIM + h * HDIM;
    const float* kbase = K + (size_t)b * SEQ * CDIM + h * HDIM;
    const float* vbase = V + (size_t)b * SEQ * CDIM + h * HDIM;

    // Stage Q tile (128x64) into Ps, then build per-warp tf32 A-fragments.
    for (int i = tid; i < QT * 16; i += 256) {
        int r  = i >> 4;
        int c4 = (i & 15) * 4;
        float4 v = *reinterpret_cast<const float4*>(&qbase[(size_t)r * CDIM + c4]);
        *reinterpret_cast<float4*>(&Ps[r * PSTR + c4]) = v;
    }
    __syncthreads();

    // q pre-rounded; *0.125 preserves mantissa -> raw bits are valid tf32.
    uint32_t qa[8][4];
    {
        const float* qp = Ps + (warp * 16 + lr) * PSTR;
#pragma unroll
        for (int ks = 0; ks < 8; ks++) {
            qa[ks][0] = __float_as_uint(qp[ks * 8 + lc] * scale);
            qa[ks][1] = __float_as_uint(qp[8 * PSTR + ks * 8 + lc] * scale);
            qa[ks][2] = __float_as_uint(qp[ks * 8 + lc + 4] * scale);
            qa[ks][3] = __float_as_uint(qp[8 * PSTR + ks * 8 + lc + 4] * scale);
        }
    }

    const uint32_t kv_row  = ((lg & 2) << 2) + li;     // +0 or +8 rows
    const uint32_t kv_col  = (lg & 1) << 4;            // +0 or +16 bytes
    const uint32_t p_row   = ((lg & 1) << 3) + li;
    const uint32_t p_col   = (lg & 2) << 3;            // +0 or +16 bytes
    const uint32_t p_addr0 = ps_u + (warp * 16 + p_row) * PSTRB + p_col;

    float m[2] = {-1e30f, -1e30f};
    float l[2] = {0.0f, 0.0f};
    float o[8][4];
#pragma unroll
    for (int nt = 0; nt < 8; nt++)
#pragma unroll
        for (int j = 0; j < 4; j++) o[nt][j] = 0.0f;

    for (int kt = 0; kt < SEQ; kt += KC) {
        // Load K chunk (row-major, float4) and V chunk (transposed, scalar).
        for (int i = tid; i < KC * 16; i += 256) {
            int r  = i >> 4;
            int c4 = (i & 15) * 4;
            float4 vk = *reinterpret_cast<const float4*>(&kbase[(size_t)(kt + r) * CDIM + c4]);
            *reinterpret_cast<float4*>(&Ks[r * PSTR + c4]) = vk;
            float4 vv = *reinterpret_cast<const float4*>(&vbase[(size_t)(kt + r) * CDIM + c4]);
            Vt[(c4 + 0) * PSTR + r] = vv.x;
            Vt[(c4 + 1) * PSTR + r] = vv.y;
            Vt[(c4 + 2) * PSTR + r] = vv.z;
            Vt[(c4 + 3) * PSTR + r] = vv.w;
        }
        __syncthreads();

        // S = (Q*scale) @ K^T
        float p[8][4];
#pragma unroll
        for (int nt = 0; nt < 8; nt++)
#pragma unroll
            for (int j = 0; j < 4; j++) p[nt][j] = 0.0f;
#pragma unroll
        for (int ntp = 0; ntp < 4; ntp++) {
            const uint32_t kaddr = ks_u + (ntp * 16 + kv_row) * PSTRB + kv_col;
#pragma unroll
            for (int ks = 0; ks < 8; ks++) {
                uint32_t b0, b1, c0, c1;
                ldsm_x4(kaddr + ks * 32, b0, b1, c0, c1);
                mma_tf32(p[2 * ntp],     qa[ks][0], qa[ks][1], qa[ks][2], qa[ks][3], b0, b1);
                mma_tf32(p[2 * ntp + 1], qa[ks][0], qa[ks][1], qa[ks][2], qa[ks][3], c0, c1);
            }
        }

        // Online softmax. Register halves: {0,1} -> row lr; {2,3} -> row lr+8.
#pragma unroll
        for (int half = 0; half < 2; half++) {
            const int j0 = half * 2;
            float mx = -1e30f;
#pragma unroll
            for (int nt = 0; nt < 8; nt++)
                mx = fmaxf(mx, fmaxf(p[nt][j0], p[nt][j0 + 1]));
            mx = fmaxf(mx, __shfl_xor_sync(0xffffffffu, mx, 1));
            mx = fmaxf(mx, __shfl_xor_sync(0xffffffffu, mx, 2));
            float mnew  = fmaxf(m[half], mx);
            float alpha = __expf(m[half] - mnew);
            float rsum = 0.0f;
#pragma unroll
            for (int nt = 0; nt < 8; nt++) {
                float p0 = __expf(p[nt][j0]     - mnew);
                float p1 = __expf(p[nt][j0 + 1] - mnew);
                p[nt][j0]     = p0;
                p[nt][j0 + 1] = p1;
                rsum += p0 + p1;
            }
            rsum += __shfl_xor_sync(0xffffffffu, rsum, 1);
            rsum += __shfl_xor_sync(0xffffffffu, rsum, 2);
            l[half] = l[half] * alpha + rsum;
            m[half] = mnew;
#pragma unroll
            for (int nt = 0; nt < 8; nt++) {
                o[nt][j0]     *= alpha;
                o[nt][j0 + 1] *= alpha;
            }
        }

        // Write tf32-rounded P to smem (rows warp*16 + lr and +8)
        {
            float* pr0 = Ps + (warp * 16 + lr) * PSTR;
            float* pr1 = pr0 + 8 * PSTR;
#pragma unroll
            for (int nt = 0; nt < 8; nt++) {
                *reinterpret_cast<uint2*>(pr0 + nt * 8 + lc * 2) =
                    make_uint2(f2tf32(p[nt][0]), f2tf32(p[nt][1]));
                *reinterpret_cast<uint2*>(pr1 + nt * 8 + lc * 2) =
                    make_uint2(f2tf32(p[nt][2]), f2tf32(p[nt][3]));
            }
        }
        __syncthreads();

        // O += P @ V
#pragma unroll
        for (int ks = 0; ks < 8; ks++) {
            uint32_t a0, a1, a2, a3;
            ldsm_x4(p_addr0 + ks * 32, a0, a1, a2, a3);
#pragma unroll
            for (int ntp = 0; ntp < 4; ntp++) {
                const uint32_t vaddr = vt_u + (ntp * 16 + kv_row) * PSTRB + kv_col + ks * 32;
                uint32_t b0, b1, c0, c1;
                ldsm_x4(vaddr, b0, b1, c0, c1);
                mma_tf32(o[2 * ntp],     a0, a1, a2, a3, b0, b1);
                mma_tf32(o[2 * ntp + 1], a0, a1, a2, a3, c0, c1);
            }
        }
        __syncthreads();
    }

    // Epilogue: normalize, split into bf16 hi/lo, write Yhi/Ylo (B,T,H,D).
    const float inv0 = 1.0f / l[0];
    const float inv1 = 1.0f / l[1];
    const size_t base0 = ((size_t)b * SEQ + qt * QT + warp * 16 + lr) * CDIM
                         + h * HDIM + lc * 2;
#pragma unroll
    for (int half = 0; half < 2; half++) {
        const float inv = half ? inv1 : inv0;
        const size_t rb = base0 + (half ? 8 * CDIM : 0);
#pragma unroll
        for (int nt = 0; nt < 8; nt++) {
            float y0 = o[nt][half * 2]     * inv;
            float y1 = o[nt][half * 2 + 1] * inv;
            __nv_bfloat16 h0 = __float2bfloat16(y0);
            __nv_bfloat16 h1 = __float2bfloat16(y1);
            __nv_bfloat16 l0 = __float2bfloat16(y0 - __bfloat162float(h0));
            __nv_bfloat16 l1 = __float2bfloat16(y1 - __bfloat162float(h1));
            *reinterpret_cast<__nv_bfloat162*>(Yhi + rb + nt * 8) = __nv_bfloat162(h0, h1);
            *reinterpret_cast<__nv_bfloat162*>(Ylo + rb + nt * 8) = __nv_bfloat162(l0, l1);
        }
    }
}

// ---------------------------------------------------------------------------
// kernel_launch
// Inputs (metadata order): x, cos, sin, Wq, Wk, Wv, Wo
// ---------------------------------------------------------------------------
extern "C" void kernel_launch(void* const* d_in, const int* in_sizes, int n_in,
                              void* d_out, int out_size)
{
    const float* x   = (const float*)d_in[0];
    const float* cs  = (const float*)d_in[1];
    const float* sn  = (const float*)d_in[2];
    const float* Wq  = (const float*)d_in[3];
    const float* Wk  = (const float*)d_in[4];
    const float* Wv  = (const float*)d_in[5];
    const float* Wo  = (const float*)d_in[6];
    float* out = (float*)d_out;

    float *q, *k, *v;
    cudaGetSymbolAddress((void**)&q, g_q);
    cudaGetSymbolAddress((void**)&k, g_k);
    cudaGetSymbolAddress((void**)&v, g_v);
    __nv_bfloat16 *xhi, *xlo, *yhi, *ylo, *whi, *wlo;
    cudaGetSymbolAddress((void**)&xhi, g_xhi);
    cudaGetSymbolAddress((void**)&xlo, g_xlo);
    cudaGetSymbolAddress((void**)&yhi, g_yhi);
    cudaGetSymbolAddress((void**)&ylo, g_ylo);
    cudaGetSymbolAddress((void**)&whi, g_whi);
    cudaGetSymbolAddress((void**)&wlo, g_wlo);

    cudaFuncSetAttribute(attn_tc_kernel, cudaFuncAttributeMaxDynamicSharedMemorySize, ATN_SMEM);
    cudaFuncSetAttribute(gemm_mma_kernel, cudaFuncAttributeMaxDynamicSharedMemorySize, GEMM_SMEM);
    cudaFuncSetAttribute(gemm_qkv_kernel, cudaFuncAttributeMaxDynamicSharedMemorySize, GEMM_SMEM);

    const size_t wsz = (size_t)CDIM * CDIM;    // 1M elements per weight

    // Split x and weights into bf16 hi/lo pairs
    {
        int n4 = (int)((size_t)MROWS * CDIM / 4);
        cvt_bf16x2_kernel<<<(n4 + 255) / 256, 256>>>(
            (const float4*)x, (__nv_bfloat162*)xhi, (__nv_bfloat162*)xlo, n4);
        int w4 = (int)(wsz / 4);
        cvt_bf16x2_kernel<<<(w4 + 255) / 256, 256>>>(
            (const float4*)Wq, (__nv_bfloat162*)(whi + 0 * wsz), (__nv_bfloat162*)(wlo + 0 * wsz), w4);
        cvt_bf16x2_kernel<<<(w4 + 255) / 256, 256>>>(
            (const float4*)Wk, (__nv_bfloat162*)(whi + 1 * wsz), (__nv_bfloat162*)(wlo + 1 * wsz), w4);
        cvt_bf16x2_kernel<<<(w4 + 255) / 256, 256>>>(
            (const float4*)Wv, (__nv_bfloat162*)(whi + 2 * wsz), (__nv_bfloat162*)(wlo + 2 * wsz), w4);
        cvt_bf16x2_kernel<<<(w4 + 255) / 256, 256>>>(
            (const float4*)Wo, (__nv_bfloat162*)(whi + 3 * wsz), (__nv_bfloat162*)(wlo + 3 * wsz), w4);
    }

    // Fused QKV GEMM + RoPE/RMS epilogue
    dim3 qkvgrid(3 * CDIM / 128, MROWS / 128);   // (24, 64)
    gemm_qkv_kernel<<<qkvgrid, 256, GEMM_SMEM>>>(xhi, xlo, whi, wlo, q, k, v, cs, sn);

    // Attention (writes bf16 hi/lo y directly)
    dim3 agrid(SEQ / QT, NHEAD, BATCH);          // (16, 16, 4)
    attn_tc_kernel<<<agrid, 256, ATN_SMEM>>>(q, k, v, yhi, ylo);

    // O projection
    dim3 ggrid(CDIM / 128, MROWS / 128);         // (8, 64)
    gemm_mma_kernel<<<ggrid, 256, GEMM_SMEM>>>(yhi, ylo, whi + 3 * wsz, wlo + 3 * wsz, out, MROWS, CDIM, CDIM);
}

// round 13
// speedup vs baseline: 1.1567x; 1.0235x over previous
#include <cuda_runtime.h>
#include <cuda_bf16.h>
#include <cstdint>
#include <cstddef>

// Problem constants (fixed shapes from reference)
#define BATCH 4
#define SEQ   2048
#define CDIM  1024
#define NHEAD 16
#define HDIM  64
#define MROWS (BATCH * SEQ)          // 8192

// ---------------------------------------------------------------------------
// Scratch (static device globals; no allocation allowed)
// ---------------------------------------------------------------------------
__device__ float g_q[(size_t)MROWS * CDIM];
__device__ float g_k[(size_t)MROWS * CDIM];
__device__ float g_v[(size_t)MROWS * CDIM];

__device__ __nv_bfloat16 g_xhi[(size_t)MROWS * CDIM];
__device__ __nv_bfloat16 g_xlo[(size_t)MROWS * CDIM];
__device__ __nv_bfloat16 g_yhi[(size_t)MROWS * CDIM];
__device__ __nv_bfloat16 g_ylo[(size_t)MROWS * CDIM];
__device__ __nv_bfloat16 g_whi[4 * (size_t)CDIM * CDIM];
__device__ __nv_bfloat16 g_wlo[4 * (size_t)CDIM * CDIM];

// ---------------------------------------------------------------------------
// fp32 -> (bf16 hi, bf16 lo) split conversion.
// ---------------------------------------------------------------------------
__device__ __forceinline__ void split4(float4 v, __nv_bfloat162* hi, __nv_bfloat162* lo)
{
    __nv_bfloat16 h0 = __float2bfloat16(v.x);
    __nv_bfloat16 h1 = __float2bfloat16(v.y);
    __nv_bfloat16 h2 = __float2bfloat16(v.z);
    __nv_bfloat16 h3 = __float2bfloat16(v.w);
    hi[0] = __nv_bfloat162(h0, h1);
    hi[1] = __nv_bfloat162(h2, h3);
    lo[0] = __nv_bfloat162(__float2bfloat16(v.x - __bfloat162float(h0)),
                           __float2bfloat16(v.y - __bfloat162float(h1)));
    lo[1] = __nv_bfloat162(__float2bfloat16(v.z - __bfloat162float(h2)),
                           __float2bfloat16(v.w - __bfloat162float(h3)));
}

__global__ __launch_bounds__(256)
void cvt_bf16x2_kernel(const float4* __restrict__ x,
                       __nv_bfloat162* __restrict__ hi,
                       __nv_bfloat162* __restrict__ lo, int n4)
{
    int i = blockIdx.x * blockDim.x + threadIdx.x;
    if (i >= n4) return;
    __nv_bfloat162 h[2], l[2];
    split4(x[i], h, l);
    hi[i * 2 + 0] = h[0]; hi[i * 2 + 1] = h[1];
    lo[i * 2 + 0] = l[0]; lo[i * 2 + 1] = l[1];
}

// All 4 weights in one launch; blockIdx.y selects the source.
__global__ __launch_bounds__(256)
void cvt_w4_kernel(const float4* __restrict__ w0, const float4* __restrict__ w1,
                   const float4* __restrict__ w2, const float4* __restrict__ w3,
                   __nv_bfloat162* __restrict__ hi,
                   __nv_bfloat162* __restrict__ lo, int n4)
{
    int i = blockIdx.x * blockDim.x + threadIdx.x;
    if (i >= n4) return;
    const float4* src = (blockIdx.y == 0) ? w0 : (blockIdx.y == 1) ? w1
                        : (blockIdx.y == 2) ? w2 : w3;
    size_t off = (size_t)blockIdx.y * n4 * 2;
    __nv_bfloat162 h[2], l[2];
    split4(src[i], h, l);
    hi[off + i * 2 + 0] = h[0]; hi[off + i * 2 + 1] = h[1];
    lo[off + i * 2 + 0] = l[0]; lo[off + i * 2 + 1] = l[1];
}

// ---------------------------------------------------------------------------
// MMA helpers (legacy warp-level tensor core path; valid on compute_103 PTX)
// ---------------------------------------------------------------------------
__device__ __forceinline__ uint32_t smem_u32(const void* p) {
    return (uint32_t)__cvta_generic_to_shared(p);
}

__device__ __forceinline__ void ldsm_x4(uint32_t addr, uint32_t& r0, uint32_t& r1,
                                        uint32_t& r2, uint32_t& r3) {
    asm volatile("ldmatrix.sync.aligned.m8n8.x4.shared.b16 {%0,%1,%2,%3}, [%4];"
                 : "=r"(r0), "=r"(r1), "=r"(r2), "=r"(r3) : "r"(addr));
}

__device__ __forceinline__ void mma_bf16(float* c, uint32_t a0, uint32_t a1,
                                         uint32_t a2, uint32_t a3,
                                         uint32_t b0, uint32_t b1) {
    asm volatile(
        "mma.sync.aligned.m16n8k16.row.col.f32.bf16.bf16.f32 "
        "{%0,%1,%2,%3}, {%4,%5,%6,%7}, {%8,%9}, {%0,%1,%2,%3};"
        : "+f"(c[0]), "+f"(c[1]), "+f"(c[2]), "+f"(c[3])
        : "r"(a0), "r"(a1), "r"(a2), "r"(a3), "r"(b0), "r"(b1));
}

__device__ __forceinline__ void mma_tf32(float* c, uint32_t a0, uint32_t a1,
                                         uint32_t a2, uint32_t a3,
                                         uint32_t b0, uint32_t b1) {
    asm volatile(
        "mma.sync.aligned.m16n8k8.row.col.f32.tf32.tf32.f32 "
        "{%0,%1,%2,%3}, {%4,%5,%6,%7}, {%8,%9}, {%0,%1,%2,%3};"
        : "+f"(c[0]), "+f"(c[1]), "+f"(c[2]), "+f"(c[3])
        : "r"(a0), "r"(a1), "r"(a2), "r"(a3), "r"(b0), "r"(b1));
}

__device__ __forceinline__ uint32_t f2tf32(float x) {
    uint32_t r;
    asm volatile("cvt.rna.tf32.f32 %0, %1;" : "=r"(r) : "f"(x));
    return r;
}
__device__ __forceinline__ float round_tf32f(float x) {
    return __uint_as_float(f2tf32(x));
}

__device__ __forceinline__ void cp_async16(uint32_t smem_dst, const void* gmem_src) {
    asm volatile("cp.async.cg.shared.global [%0], [%1], 16;"
                 :: "r"(smem_dst), "l"(gmem_src) : "memory");
}
__device__ __forceinline__ void cp_async_commit_wait0() {
    asm volatile("cp.async.commit_group;" ::: "memory");
    asm volatile("cp.async.wait_group 0;" ::: "memory");
}

// ---------------------------------------------------------------------------
// Shared bf16x3 GEMM mainloop (NT): acc = sum_k A[m,k]*B[n,k].
// Tile: 128x128, BK=64 bf16. 8 warps in 4(m) x 2(n); warp tile 32x64.
// Smem rows padded to 72 bf16 (144B) -> conflict-free ldmatrix.
// ---------------------------------------------------------------------------
#define GBK       64
#define LDS_STR   72                      // bf16 elements per smem row
#define LDS_STRB  (LDS_STR * 2)           // 144 bytes
#define TILE_B    (128 * LDS_STRB)        // 18432 bytes per operand tile
#define OFF_AHI   0
#define OFF_ALO   (1 * TILE_B)
#define OFF_BHI   (2 * TILE_B)
#define OFF_BLO   (3 * TILE_B)
#define GEMM_SMEM (4 * TILE_B)            // 73728 bytes

__device__ __forceinline__ void gemm_mainloop(
    char* sm, uint32_t sbase, int tid, int warp, int lane,
    const char* pAh, const char* pAl, const char* pBh, const char* pBl,
    int K, float acc[2][8][4])
{
    const int wm = warp & 3;
    const int wn = warp >> 2;
    const size_t rowb = (size_t)K * 2;
    const int lrow = lane & 15;
    const int lcol = (lane >> 4) * 16;

    const int nch = K / GBK;
    for (int ch = 0; ch < nch; ch++) {
        const size_t koff = (size_t)ch * (GBK * 2);   // bytes
#pragma unroll
        for (int it = 0; it < 4; it++) {
            int i  = tid + it * 256;       // 0..1023
            int r  = i >> 3;
            int cb = (i & 7) * 16;
            size_t   go = (size_t)r * rowb + koff + cb;
            uint32_t so = r * LDS_STRB + cb;
            cp_async16(sbase + OFF_AHI + so, pAh + go);
            cp_async16(sbase + OFF_ALO + so, pAl + go);
            cp_async16(sbase + OFF_BHI + so, pBh + go);
            cp_async16(sbase + OFF_BLO + so, pBl + go);
        }
        cp_async_commit_wait0();
        __syncthreads();

#pragma unroll
        for (int kk = 0; kk < GBK / 16; kk++) {
            const uint32_t kbyte = kk * 32 + lcol;
            uint32_t bh[8][2], bl[8][2];
#pragma unroll
            for (int np = 0; np < 4; np++) {
                uint32_t baddr = sbase + OFF_BHI +
                                 (wn * 64 + np * 16 + lrow) * LDS_STRB + kbyte;
                ldsm_x4(baddr, bh[np * 2][0], bh[np * 2 + 1][0],
                               bh[np * 2][1], bh[np * 2 + 1][1]);
                uint32_t laddr = baddr + (OFF_BLO - OFF_BHI);
                ldsm_x4(laddr, bl[np * 2][0], bl[np * 2 + 1][0],
                               bl[np * 2][1], bl[np * 2 + 1][1]);
            }
#pragma unroll
            for (int mt = 0; mt < 2; mt++) {
                uint32_t aaddr = sbase + OFF_AHI +
                                 (wm * 32 + mt * 16 + lrow) * LDS_STRB + kbyte;
                uint32_t ah0, ah1, ah2, ah3, al0, al1, al2, al3;
                ldsm_x4(aaddr, ah0, ah1, ah2, ah3);
                ldsm_x4(aaddr + (OFF_ALO - OFF_AHI), al0, al1, al2, al3);
#pragma unroll
                for (int nt = 0; nt < 8; nt++) {
                    mma_bf16(acc[mt][nt], ah0, ah1, ah2, ah3, bh[nt][0], bh[nt][1]);
                    mma_bf16(acc[mt][nt], ah0, ah1, ah2, ah3, bl[nt][0], bl[nt][1]);
                    mma_bf16(acc[mt][nt], al0, al1, al2, al3, bh[nt][0], bh[nt][1]);
                }
            }
        }
        __syncthreads();
    }
}

// ---------------------------------------------------------------------------
// Fused QKV GEMM: one launch computes q, k, v (blockIdx.x>>3 selects weight).
// Epilogue applies RoPE + RMSNorm + tf32 rounding for q/k, rounding for v.
// ---------------------------------------------------------------------------
__global__ __launch_bounds__(256, 2)
void gemm_qkv_kernel(const __nv_bfloat16* __restrict__ Ahi,
                     const __nv_bfloat16* __restrict__ Alo,
                     const __nv_bfloat16* __restrict__ Whi,   // [3][CDIM*CDIM]
                     const __nv_bfloat16* __restrict__ Wlo,
                     float* __restrict__ q, float* __restrict__ k,
                     float* __restrict__ v,
                     const float* __restrict__ cs, const float* __restrict__ sn)
{
    extern __shared__ char sm[];
    const int tid  = threadIdx.x;
    const int warp = tid >> 5;
    const int lane = tid & 31;
    const int wm   = warp & 3;
    const int wn   = warp >> 2;
    const int wsel = blockIdx.x >> 3;            // 0=q, 1=k, 2=v
    const int n0   = (blockIdx.x & 7) * 128;
    const int m0   = blockIdx.y * 128;
    const int K    = CDIM;
    const size_t wsz = (size_t)CDIM * CDIM;

    const uint32_t sbase = smem_u32(sm);

    float acc[2][8][4];
#pragma unroll
    for (int i = 0; i < 2; i++)
#pragma unroll
        for (int j = 0; j < 8; j++)
#pragma unroll
            for (int t = 0; t < 4; t++) acc[i][j][t] = 0.0f;

    gemm_mainloop(sm, sbase, tid, warp, lane,
                  (const char*)(Ahi + (size_t)m0 * K),
                  (const char*)(Alo + (size_t)m0 * K),
                  (const char*)(Whi + wsel * wsz + (size_t)n0 * K),
                  (const char*)(Wlo + wsel * wsz + (size_t)n0 * K),
                  K, acc);

    float* C = (wsel == 0) ? q : (wsel == 1) ? k : v;
    const int qrow = lane >> 2;
    const int qcol = (lane & 3) * 2;

    if (wsel < 2) {
#pragma unroll
        for (int mt = 0; mt < 2; mt++) {
#pragma unroll
            for (int rh = 0; rh < 2; rh++) {
                const int j0  = rh * 2;
                const int row = m0 + wm * 32 + mt * 16 + qrow + rh * 8;
                const int t   = row & (SEQ - 1);
                const float* cst = cs + t * HDIM;
                const float* snt = sn + t * HDIM;
#pragma unroll
                for (int nt = 0; nt < 4; nt++) {
#pragma unroll
                    for (int j = 0; j < 2; j++) {
                        const int d = nt * 8 + qcol + j;        // < 32
                        float x1 = acc[mt][nt][j0 + j];
                        float x2 = acc[mt][nt + 4][j0 + j];
                        float r1 = x1 * cst[d]      - x2 * snt[d];
                        float r2 = x2 * cst[d + 32] + x1 * snt[d + 32];
                        acc[mt][nt][j0 + j]     = r1;
                        acc[mt][nt + 4][j0 + j] = r2;
                    }
                }
                float ss = 0.0f;
#pragma unroll
                for (int nt = 0; nt < 8; nt++)
                    ss += acc[mt][nt][j0] * acc[mt][nt][j0]
                        + acc[mt][nt][j0 + 1] * acc[mt][nt][j0 + 1];
                ss += __shfl_xor_sync(0xffffffffu, ss, 1);
                ss += __shfl_xor_sync(0xffffffffu, ss, 2);
                const float inv = rsqrtf(ss * (1.0f / 64.0f) + 1e-6f);
                float* crow = C + (size_t)row * CDIM + n0 + wn * 64;
#pragma unroll
                for (int nt = 0; nt < 8; nt++) {
                    *reinterpret_cast<float2*>(crow + nt * 8 + qcol) = make_float2(
                        round_tf32f(acc[mt][nt][j0] * inv),
                        round_tf32f(acc[mt][nt][j0 + 1] * inv));
                }
            }
        }
    } else {
#pragma unroll
        for (int mt = 0; mt < 2; mt++) {
#pragma unroll
            for (int rh = 0; rh < 2; rh++) {
                const int j0  = rh * 2;
                const int row = m0 + wm * 32 + mt * 16 + qrow + rh * 8;
                float* crow = C + (size_t)row * CDIM + n0 + wn * 64;
#pragma unroll
                for (int nt = 0; nt < 8; nt++) {
                    *reinterpret_cast<float2*>(crow + nt * 8 + qcol) = make_float2(
                        round_tf32f(acc[mt][nt][j0]),
                        round_tf32f(acc[mt][nt][j0 + 1]));
                }
            }
        }
    }
}

// ---------------------------------------------------------------------------
// Generic bf16x3 GEMM (for the O-projection): C = A @ B^T, fp32 out.
// ---------------------------------------------------------------------------
__global__ __launch_bounds__(256, 2)
void gemm_mma_kernel(const __nv_bfloat16* __restrict__ Ahi,
                     const __nv_bfloat16* __restrict__ Alo,
                     const __nv_bfloat16* __restrict__ Bhi,
                     const __nv_bfloat16* __restrict__ Blo,
                     float* __restrict__ C, int M, int N, int K)
{
    extern __shared__ char sm[];
    const int tid  = threadIdx.x;
    const int warp = tid >> 5;
    const int lane = tid & 31;
    const int wm   = warp & 3;
    const int wn   = warp >> 2;
    const int m0   = blockIdx.y * 128;
    const int n0   = blockIdx.x * 128;

    const uint32_t sbase = smem_u32(sm);

    float acc[2][8][4];
#pragma unroll
    for (int i = 0; i < 2; i++)
#pragma unroll
        for (int j = 0; j < 8; j++)
#pragma unroll
            for (int t = 0; t < 4; t++) acc[i][j][t] = 0.0f;

    gemm_mainloop(sm, sbase, tid, warp, lane,
                  (const char*)(Ahi + (size_t)m0 * K),
                  (const char*)(Alo + (size_t)m0 * K),
                  (const char*)(Bhi + (size_t)n0 * K),
                  (const char*)(Blo + (size_t)n0 * K),
                  K, acc);

    const int qrow = lane >> 2;
    const int qcol = (lane & 3) * 2;
#pragma unroll
    for (int mt = 0; mt < 2; mt++) {
        const int r0 = m0 + wm * 32 + mt * 16 + qrow;
#pragma unroll
        for (int nt = 0; nt < 8; nt++) {
            const int c = n0 + wn * 64 + nt * 8 + qcol;
            *reinterpret_cast<float2*>(&C[(size_t)r0 * N + c]) =
                make_float2(acc[mt][nt][0], acc[mt][nt][1]);
            *reinterpret_cast<float2*>(&C[(size_t)(r0 + 8) * N + c]) =
                make_float2(acc[mt][nt][2], acc[mt][nt][3]);
        }
    }
}

// ---------------------------------------------------------------------------
// Tensor-core flash attention (tf32 mma, fp32 accum).
// FIXED-MAX softmax: after RMS-norm, |q|=|k|=8 exactly, so every score
// s = q.k/8 lies in [-8, 8] (Cauchy-Schwarz). Softmax is shift-invariant,
// so p = exp(s - 8) needs no running max, no rescaling, and l is a plain
// associative sum reduced ONCE after the k-loop.
// All fragments via ldmatrix.x4. P round trip is warp-local -> syncwarp.
// Epilogue writes bf16 hi/lo split of y directly.
// ---------------------------------------------------------------------------
#define QT    128
#define KC    64
#define PSTR  68
#define PSTRB (PSTR * 4)
#define ATN_SMEM ((KC + KC + QT) * PSTR * (int)sizeof(float))   // 69632

__global__ __launch_bounds__(256)
void attn_tc_kernel(const float* __restrict__ Q, const float* __restrict__ K,
                    const float* __restrict__ V,
                    __nv_bfloat16* __restrict__ Yhi,
                    __nv_bfloat16* __restrict__ Ylo)
{
    extern __shared__ float smf[];
    float* Ks = smf;                   // [KC][PSTR]   k-contiguous
    float* Vt = Ks + KC * PSTR;        // [HDIM][PSTR] TRANSPOSED: row=d, col=kk
    float* Ps = Vt + KC * PSTR;        // [QT][PSTR]   (also Q staging)

    const int b    = blockIdx.z;
    const int h    = blockIdx.y;
    const int qt   = blockIdx.x;
    const int tid  = threadIdx.x;
    const int warp = tid >> 5;
    const int lane = tid & 31;
    const int lr   = lane >> 2;        // 0..7
    const int lc   = lane & 3;         // 0..3
    const int lg   = lane >> 3;        // ldmatrix lane group 0..3
    const int li   = lane & 7;         // row within group
    const float scale = 0.125f;        // 1/sqrt(64), exact power of two

    const uint32_t ks_u = smem_u32(Ks);
    const uint32_t vt_u = smem_u32(Vt);
    const uint32_t ps_u = smem_u32(Ps);

    const float* qbase = Q + ((size_t)b * SEQ + qt * QT) * CDIM + h * HDIM;
    const float* kbase = K + (size_t)b * SEQ * CDIM + h * HDIM;
    const float* vbase = V + (size_t)b * SEQ * CDIM + h * HDIM;

    // Stage Q tile (128x64) into Ps, then build per-warp tf32 A-fragments.
    for (int i = tid; i < QT * 16; i += 256) {
        int r  = i >> 4;
        int c4 = (i & 15) * 4;
        float4 v = *reinterpret_cast<const float4*>(&qbase[(size_t)r * CDIM + c4]);
        *reinterpret_cast<float4*>(&Ps[r * PSTR + c4]) = v;
    }
    __syncthreads();

    // q pre-rounded; *0.125 preserves mantissa -> raw bits are valid tf32.
    uint32_t qa[8][4];
    {
        const float* qp = Ps + (warp * 16 + lr) * PSTR;
#pragma unroll
        for (int ks = 0; ks < 8; ks++) {
            qa[ks][0] = __float_as_uint(qp[ks * 8 + lc] * scale);
            qa[ks][1] = __float_as_uint(qp[8 * PSTR + ks * 8 + lc] * scale);
            qa[ks][2] = __float_as_uint(qp[ks * 8 + lc + 4] * scale);
            qa[ks][3] = __float_as_uint(qp[8 * PSTR + ks * 8 + lc + 4] * scale);
        }
    }

    const uint32_t kv_row  = ((lg & 2) << 2) + li;     // +0 or +8 rows
    const uint32_t kv_col  = (lg & 1) << 4;            // +0 or +16 bytes
    const uint32_t p_row   = ((lg & 1) << 3) + li;
    const uint32_t p_col   = (lg & 2) << 3;            // +0 or +16 bytes
    const uint32_t p_addr0 = ps_u + (warp * 16 + p_row) * PSTRB + p_col;

    float l[2] = {0.0f, 0.0f};
    float o[8][4];
#pragma unroll
    for (int nt = 0; nt < 8; nt++)
#pragma unroll
        for (int j = 0; j < 4; j++) o[nt][j] = 0.0f;

    for (int kt = 0; kt < SEQ; kt += KC) {
        // Load K chunk (row-major, float4) and V chunk (transposed, scalar).
        for (int i = tid; i < KC * 16; i += 256) {
            int r  = i >> 4;
            int c4 = (i & 15) * 4;
            float4 vk = *reinterpret_cast<const float4*>(&kbase[(size_t)(kt + r) * CDIM + c4]);
            *reinterpret_cast<float4*>(&Ks[r * PSTR + c4]) = vk;
            float4 vv = *reinterpret_cast<const float4*>(&vbase[(size_t)(kt + r) * CDIM + c4]);
            Vt[(c4 + 0) * PSTR + r] = vv.x;
            Vt[(c4 + 1) * PSTR + r] = vv.y;
            Vt[(c4 + 2) * PSTR + r] = vv.z;
            Vt[(c4 + 3) * PSTR + r] = vv.w;
        }
        __syncthreads();

        // S = (Q*scale) @ K^T
        float p[8][4];
#pragma unroll
        for (int nt = 0; nt < 8; nt++)
#pragma unroll
            for (int j = 0; j < 4; j++) p[nt][j] = 0.0f;
#pragma unroll
        for (int ntp = 0; ntp < 4; ntp++) {
            const uint32_t kaddr = ks_u + (ntp * 16 + kv_row) * PSTRB + kv_col;
#pragma unroll
            for (int ks = 0; ks < 8; ks++) {
                uint32_t b0, b1, c0, c1;
                ldsm_x4(kaddr + ks * 32, b0, b1, c0, c1);
                mma_tf32(p[2 * ntp],     qa[ks][0], qa[ks][1], qa[ks][2], qa[ks][3], b0, b1);
                mma_tf32(p[2 * ntp + 1], qa[ks][0], qa[ks][1], qa[ks][2], qa[ks][3], c0, c1);
            }
        }

        // Fixed-max softmax: p = exp(s - 8); accumulate per-thread l.
#pragma unroll
        for (int half = 0; half < 2; half++) {
            const int j0 = half * 2;
            float rsum = 0.0f;
#pragma unroll
            for (int nt = 0; nt < 8; nt++) {
                float p0 = __expf(p[nt][j0]     - 8.0f);
                float p1 = __expf(p[nt][j0 + 1] - 8.0f);
                p[nt][j0]     = p0;
                p[nt][j0 + 1] = p1;
                rsum += p0 + p1;
            }
            l[half] += rsum;
        }

        // Write tf32-rounded P to smem (rows warp*16 + lr and +8).
        // Warp-local round trip: only this warp reads these rows back.
        {
            float* pr0 = Ps + (warp * 16 + lr) * PSTR;
            float* pr1 = pr0 + 8 * PSTR;
#pragma unroll
            for (int nt = 0; nt < 8; nt++) {
                *reinterpret_cast<uint2*>(pr0 + nt * 8 + lc * 2) =
                    make_uint2(f2tf32(p[nt][0]), f2tf32(p[nt][1]));
                *reinterpret_cast<uint2*>(pr1 + nt * 8 + lc * 2) =
                    make_uint2(f2tf32(p[nt][2]), f2tf32(p[nt][3]));
            }
        }
        __syncwarp();

        // O += P @ V
#pragma unroll
        for (int ks = 0; ks < 8; ks++) {
            uint32_t a0, a1, a2, a3;
            ldsm_x4(p_addr0 + ks * 32, a0, a1, a2, a3);
#pragma unroll
            for (int ntp = 0; ntp < 4; ntp++) {
                const uint32_t vaddr = vt_u + (ntp * 16 + kv_row) * PSTRB + kv_col + ks * 32;
                uint32_t b0, b1, c0, c1;
                ldsm_x4(vaddr, b0, b1, c0, c1);
                mma_tf32(o[2 * ntp],     a0, a1, a2, a3, b0, b1);
                mma_tf32(o[2 * ntp + 1], a0, a1, a2, a3, c0, c1);
            }
        }
        __syncthreads();
    }

    // Final l reduction over the quad (cols are spread across lc lanes).
#pragma unroll
    for (int half = 0; half < 2; half++) {
        l[half] += __shfl_xor_sync(0xffffffffu, l[half], 1);
        l[half] += __shfl_xor_sync(0xffffffffu, l[half], 2);
    }

    // Epilogue: normalize, split into bf16 hi/lo, write Yhi/Ylo (B,T,H,D).
    const float inv0 = 1.0f / l[0];
    const float inv1 = 1.0f / l[1];
    const size_t base0 = ((size_t)b * SEQ + qt * QT + warp * 16 + lr) * CDIM
                         + h * HDIM + lc * 2;
#pragma unroll
    for (int half = 0; half < 2; half++) {
        const float inv = half ? inv1 : inv0;
        const size_t rb = base0 + (half ? 8 * CDIM : 0);
#pragma unroll
        for (int nt = 0; nt < 8; nt++) {
            float y0 = o[nt][half * 2]     * inv;
            float y1 = o[nt][half * 2 + 1] * inv;
            __nv_bfloat16 h0 = __float2bfloat16(y0);
            __nv_bfloat16 h1 = __float2bfloat16(y1);
            __nv_bfloat16 l0 = __float2bfloat16(y0 - __bfloat162float(h0));
            __nv_bfloat16 l1 = __float2bfloat16(y1 - __bfloat162float(h1));
            *reinterpret_cast<__nv_bfloat162*>(Yhi + rb + nt * 8) = __nv_bfloat162(h0, h1);
            *reinterpret_cast<__nv_bfloat162*>(Ylo + rb + nt * 8) = __nv_bfloat162(l0, l1);
        }
    }
}

// ---------------------------------------------------------------------------
// kernel_launch
// Inputs (metadata order): x, cos, sin, Wq, Wk, Wv, Wo
// ---------------------------------------------------------------------------
extern "C" void kernel_launch(void* const* d_in, const int* in_sizes, int n_in,
                              void* d_out, int out_size)
{
    const float* x   = (const float*)d_in[0];
    const float* cs  = (const float*)d_in[1];
    const float* sn  = (const float*)d_in[2];
    const float* Wq  = (const float*)d_in[3];
    const float* Wk  = (const float*)d_in[4];
    const float* Wv  = (const float*)d_in[5];
    const float* Wo  = (const float*)d_in[6];
    float* out = (float*)d_out;

    float *q, *k, *v;
    cudaGetSymbolAddress((void**)&q, g_q);
    cudaGetSymbolAddress((void**)&k, g_k);
    cudaGetSymbolAddress((void**)&v, g_v);
    __nv_bfloat16 *xhi, *xlo, *yhi, *ylo, *whi, *wlo;
    cudaGetSymbolAddress((void**)&xhi, g_xhi);
    cudaGetSymbolAddress((void**)&xlo, g_xlo);
    cudaGetSymbolAddress((void**)&yhi, g_yhi);
    cudaGetSymbolAddress((void**)&ylo, g_ylo);
    cudaGetSymbolAddress((void**)&whi, g_whi);
    cudaGetSymbolAddress((void**)&wlo, g_wlo);

    cudaFuncSetAttribute(attn_tc_kernel, cudaFuncAttributeMaxDynamicSharedMemorySize, ATN_SMEM);
    cudaFuncSetAttribute(gemm_mma_kernel, cudaFuncAttributeMaxDynamicSharedMemorySize, GEMM_SMEM);
    cudaFuncSetAttribute(gemm_qkv_kernel, cudaFuncAttributeMaxDynamicSharedMemorySize, GEMM_SMEM);

    const size_t wsz = (size_t)CDIM * CDIM;    // 1M elements per weight

    // Split x (one launch) and all 4 weights (one fused launch) into hi/lo.
    {
        int n4 = (int)((size_t)MROWS * CDIM / 4);
        cvt_bf16x2_kernel<<<(n4 + 255) / 256, 256>>>(
            (const float4*)x, (__nv_bfloat162*)xhi, (__nv_bfloat162*)xlo, n4);
        int w4 = (int)(wsz / 4);
        dim3 wgrid((w4 + 255) / 256, 4);
        cvt_w4_kernel<<<wgrid, 256>>>(
            (const float4*)Wq, (const float4*)Wk, (const float4*)Wv, (const float4*)Wo,
            (__nv_bfloat162*)whi, (__nv_bfloat162*)wlo, w4);
    }

    // Fused QKV GEMM + RoPE/RMS epilogue
    dim3 qkvgrid(3 * CDIM / 128, MROWS / 128);   // (24, 64)
    gemm_qkv_kernel<<<qkvgrid, 256, GEMM_SMEM>>>(xhi, xlo, whi, wlo, q, k, v, cs, sn);

    // Attention (writes bf16 hi/lo y directly)
    dim3 agrid(SEQ / QT, NHEAD, BATCH);          // (16, 16, 4)
    attn_tc_kernel<<<agrid, 256, ATN_SMEM>>>(q, k, v, yhi, ylo);

    // O projection
    dim3 ggrid(CDIM / 128, MROWS / 128);         // (8, 64)
    gemm_mma_kernel<<<ggrid, 256, GEMM_SMEM>>>(yhi, ylo, whi + 3 * wsz, wlo + 3 * wsz, out, MROWS, CDIM, CDIM);
}